// round 1
// baseline (speedup 1.0000x reference)
#include <cuda_runtime.h>
#include <math.h>

#define DD 96
#define LL 9216
#define KK 4
#define NN 16
#define RR 6
#define CC 38
#define LC 16
#define NC 576   // LL/LC
#define KD 384   // KK*DD

// scratch (no allocations allowed)
__device__ float  g_xT[DD*LL];          // transposed image per d
__device__ float  g_BC[KK*LL*32];       // (k,l,[B0..15,C0..15])
__device__ float2 g_dx[KK*LL*DD];       // (k,l,d) -> (delta, x)
__device__ float  g_Sd[NC*KD];          // per-chunk sum of delta
__device__ float  g_H [NC*KD*NN];       // per-chunk h (pass1) then h_in (pass2)
__device__ float  g_y [KK*LL*DD];       // (k,l,d) scan output

// ---------------------------------------------------------------------------
// Kernel T: per-d HW transpose of x
// ---------------------------------------------------------------------------
__global__ void k_transpose(const float* __restrict__ x){
    __shared__ float tile[32][33];
    int d  = blockIdx.z;
    int h0 = blockIdx.x*32, w0 = blockIdx.y*32;
    int tx = threadIdx.x,  ty = threadIdx.y;
    const float* xp = x    + (size_t)d*LL;
    float*       op = g_xT + (size_t)d*LL;
    #pragma unroll
    for (int i=0;i<4;i++) tile[ty+8*i][tx] = xp[(h0+ty+8*i)*96 + w0+tx];
    __syncthreads();
    #pragma unroll
    for (int i=0;i<4;i++) op[(w0+ty+8*i)*96 + h0+tx] = tile[tx][ty+8*i];
}

// ---------------------------------------------------------------------------
// Kernel A: projections. Block = (32 l-values, one k).
//  x_dbl[c,l] = sum_d W[k,c,d] * xs[k,d,l]   (C=38)
//  delta[d,l] = softplus(sum_r x_dbl[r,l]*Wdt[k,d,r] + bias[k,d])
// Writes (delta,x) pairs in (k,l,d) layout and B/C in (k,l,32) layout.
// ---------------------------------------------------------------------------
__global__ __launch_bounds__(256) void k_proj(
    const float* __restrict__ x,  const float* __restrict__ W,
    const float* __restrict__ dtw,const float* __restrict__ dtb)
{
    __shared__ float xs_s [96*33];
    __shared__ float Wt_s [96*40];
    __shared__ float dbl_s[40*33];
    __shared__ float Wdt_s[96*6];
    __shared__ float bias_s[96];

    int k   = blockIdx.y;
    int l0  = blockIdx.x*32;
    int tid = threadIdx.x;
    const float* src = (k & 1) ? g_xT : x;

    for (int idx=tid; idx<96*32; idx+=256){
        int d = idx>>5, li = idx&31;
        int l = l0+li;
        int ls = (k<2) ? l : (LL-1-l);
        xs_s[d*33+li] = src[(size_t)d*LL + ls];
    }
    for (int idx=tid; idx<CC*96; idx+=256){
        int c = idx/96, d = idx - c*96;
        Wt_s[d*40+c] = W[(k*CC+c)*96 + d];
    }
    for (int idx=tid; idx<96*6; idx+=256) Wdt_s[idx] = dtw[k*576 + idx];
    if (tid < 96) bias_s[tid] = dtb[k*96 + tid];
    __syncthreads();

    int lane = tid & 31, wrp = tid >> 5;
    #pragma unroll
    for (int qq=0; qq<2; qq++){
        int q = wrp + qq*8;
        if (q < 10){
            int c0 = q*4;
            float ax=0.f, ay=0.f, az=0.f, aw=0.f;
            for (int d=0; d<96; d++){
                float  xv = xs_s[d*33+lane];
                float4 wv = *(const float4*)&Wt_s[d*40+c0];
                ax = fmaf(wv.x, xv, ax); ay = fmaf(wv.y, xv, ay);
                az = fmaf(wv.z, xv, az); aw = fmaf(wv.w, xv, aw);
            }
            dbl_s[(c0+0)*33+lane] = ax;
            dbl_s[(c0+1)*33+lane] = ay;
            dbl_s[(c0+2)*33+lane] = az;
            dbl_s[(c0+3)*33+lane] = aw;
        }
    }
    __syncthreads();

    // B,C out: c in [6,38)
    for (int idx=tid; idx<32*32; idx+=256){
        int li = idx>>5, j = idx&31;
        g_BC[((size_t)k*LL + l0+li)*32 + j] = dbl_s[(6+j)*33 + li];
    }
    // delta + x out
    for (int idx=tid; idx<96*32; idx+=256){
        int d = idx%96, li = idx/96;
        float acc = bias_s[d];
        #pragma unroll
        for (int r=0; r<6; r++) acc = fmaf(dbl_s[r*33+li], Wdt_s[d*6+r], acc);
        float sp = (acc > 20.f) ? acc : log1pf(__expf(acc));
        g_dx[((size_t)k*LL + l0+li)*96 + d] = make_float2(sp, xs_s[d*33+li]);
    }
}

// ---------------------------------------------------------------------------
// Pass 1: per-chunk local scan (h_in = 0). Block = (chunk, k), thread = d.
// Stores sum(delta) and final h[16]. decay product = exp(A_n * sum delta).
// ---------------------------------------------------------------------------
__global__ __launch_bounds__(96) void k_scan1(const float* __restrict__ A_logs){
    __shared__ float BC_s[LC*32];
    int k = blockIdx.y, ch = blockIdx.x;
    int c0 = ch*LC;
    int d  = threadIdx.x;
    for (int idx=d; idx<LC*32; idx+=96)
        BC_s[idx] = g_BC[((size_t)k*LL + c0)*32 + idx];
    __syncthreads();

    float Aa[NN];
    #pragma unroll
    for (int n=0;n<NN;n++) Aa[n] = -__expf(A_logs[(k*96+d)*NN + n]);
    float h[NN];
    #pragma unroll
    for (int n=0;n<NN;n++) h[n] = 0.f;
    float sd = 0.f;

    const float2* dxp = g_dx + ((size_t)k*LL + c0)*96 + d;
    #pragma unroll 2
    for (int li=0; li<LC; li++){
        float2 dv = dxp[(size_t)li*96];
        float delta = dv.x;
        float du    = dv.x*dv.y;
        sd += delta;
        const float4* bp = (const float4*)&BC_s[li*32];
        float4 b0=bp[0], b1=bp[1], b2=bp[2], b3=bp[3];
        float Bv[16] = {b0.x,b0.y,b0.z,b0.w, b1.x,b1.y,b1.z,b1.w,
                        b2.x,b2.y,b2.z,b2.w, b3.x,b3.y,b3.z,b3.w};
        #pragma unroll
        for (int n=0;n<NN;n++)
            h[n] = fmaf(h[n], __expf(delta*Aa[n]), du*Bv[n]);
    }
    int base = ch*KD + k*96 + d;
    g_Sd[base] = sd;
    float4* hp = (float4*)&g_H[(size_t)base*16];
    hp[0] = make_float4(h[0] ,h[1] ,h[2] ,h[3] );
    hp[1] = make_float4(h[4] ,h[5] ,h[6] ,h[7] );
    hp[2] = make_float4(h[8] ,h[9] ,h[10],h[11]);
    hp[3] = make_float4(h[12],h[13],h[14],h[15]);
}

// ---------------------------------------------------------------------------
// Pass 2: combine chunk summaries. 6144 threads, one per (k,d,n) sequence.
// Writes each chunk's INCOMING state in-place into g_H.
// ---------------------------------------------------------------------------
__global__ void k_scan2(const float* __restrict__ A_logs){
    int t  = blockIdx.x*128 + threadIdx.x;   // 0..6143
    int n  = t & 15;
    int kd = t >> 4;
    float Av = -__expf(A_logs[kd*16 + n]);
    float h = 0.f;
    for (int ch=0; ch<NC; ch++){
        int base = ch*KD + kd;
        float q = g_H[(size_t)base*16 + n];
        float P = __expf(Av * g_Sd[base]);
        g_H[(size_t)base*16 + n] = h;
        h = fmaf(P, h, q);
    }
}

// ---------------------------------------------------------------------------
// Pass 3: replay chunk with correct h_in, emit y = sum_n h_n*C_n + x*Ds.
// ---------------------------------------------------------------------------
__global__ __launch_bounds__(96) void k_scan3(const float* __restrict__ A_logs,
                                              const float* __restrict__ Ds){
    __shared__ float BC_s[LC*32];
    int k = blockIdx.y, ch = blockIdx.x;
    int c0 = ch*LC;
    int d  = threadIdx.x;
    for (int idx=d; idx<LC*32; idx+=96)
        BC_s[idx] = g_BC[((size_t)k*LL + c0)*32 + idx];
    __syncthreads();

    float Aa[NN];
    #pragma unroll
    for (int n=0;n<NN;n++) Aa[n] = -__expf(A_logs[(k*96+d)*NN + n]);

    int base = ch*KD + k*96 + d;
    const float4* hp = (const float4*)&g_H[(size_t)base*16];
    float4 h0v=hp[0], h1v=hp[1], h2v=hp[2], h3v=hp[3];
    float h[16] = {h0v.x,h0v.y,h0v.z,h0v.w, h1v.x,h1v.y,h1v.z,h1v.w,
                   h2v.x,h2v.y,h2v.z,h2v.w, h3v.x,h3v.y,h3v.z,h3v.w};
    float Dsv = Ds[k*96 + d];

    const float2* dxp = g_dx + ((size_t)k*LL + c0)*96 + d;
    float*        yp  = g_y  + ((size_t)k*LL + c0)*96 + d;
    #pragma unroll 2
    for (int li=0; li<LC; li++){
        float2 dv = dxp[(size_t)li*96];
        float delta = dv.x, xv = dv.y;
        float du = delta*xv;
        const float4* bp = (const float4*)&BC_s[li*32];
        float4 b0=bp[0], b1=bp[1], b2=bp[2], b3=bp[3];
        float4 q0=bp[4], q1=bp[5], q2=bp[6], q3=bp[7];
        float Bv[16] = {b0.x,b0.y,b0.z,b0.w, b1.x,b1.y,b1.z,b1.w,
                        b2.x,b2.y,b2.z,b2.w, b3.x,b3.y,b3.z,b3.w};
        float Cv[16] = {q0.x,q0.y,q0.z,q0.w, q1.x,q1.y,q1.z,q1.w,
                        q2.x,q2.y,q2.z,q2.w, q3.x,q3.y,q3.z,q3.w};
        float y = xv*Dsv;
        #pragma unroll
        for (int n=0;n<NN;n++){
            h[n] = fmaf(h[n], __expf(delta*Aa[n]), du*Bv[n]);
            y    = fmaf(h[n], Cv[n], y);
        }
        yp[(size_t)li*96] = y;
    }
}

// ---------------------------------------------------------------------------
// Final: combine 4 directions (reverse/transpose-back), layernorm over D=96.
// Block per output l, 96 threads (= d).
// ---------------------------------------------------------------------------
__global__ __launch_bounds__(96) void k_final(const float* __restrict__ lnw,
                                              const float* __restrict__ lnb,
                                              float* __restrict__ out){
    int l  = blockIdx.x;
    int d  = threadIdx.x;
    int hh = l/96, ww = l - hh*96;
    int lt = ww*96 + hh;
    float v = g_y[(size_t)(0*LL + l)           *96 + d]
            + g_y[(size_t)(2*LL + (LL-1-l))    *96 + d]
            + g_y[(size_t)(1*LL + lt)          *96 + d]
            + g_y[(size_t)(3*LL + (LL-1-lt))   *96 + d];
    float s = v, ss = v*v;
    #pragma unroll
    for (int o=16;o>0;o>>=1){
        s  += __shfl_xor_sync(0xffffffffu, s,  o);
        ss += __shfl_xor_sync(0xffffffffu, ss, o);
    }
    __shared__ float rs[3], rss[3];
    int wid = d>>5;
    if ((d&31)==0){ rs[wid]=s; rss[wid]=ss; }
    __syncthreads();
    float tot  = rs[0]+rs[1]+rs[2];
    float tot2 = rss[0]+rss[1]+rss[2];
    float mu  = tot*(1.f/96.f);
    float var = fmaxf(tot2*(1.f/96.f) - mu*mu, 0.f);
    float r   = rsqrtf(var + 1e-5f);
    out[(size_t)l*96 + d] = (v-mu)*r*lnw[d] + lnb[d];
}

// ---------------------------------------------------------------------------
extern "C" void kernel_launch(void* const* d_in, const int* in_sizes, int n_in,
                              void* d_out, int out_size)
{
    const float* x   = (const float*)d_in[0];
    const float* W   = (const float*)d_in[1];
    const float* dtw = (const float*)d_in[2];
    const float* dtb = (const float*)d_in[3];
    const float* Al  = (const float*)d_in[4];
    const float* Ds  = (const float*)d_in[5];
    const float* lnw = (const float*)d_in[6];
    const float* lnb = (const float*)d_in[7];
    float* out = (float*)d_out;

    k_transpose<<<dim3(3,3,96), dim3(32,8)>>>(x);
    k_proj     <<<dim3(LL/32, KK), 256>>>(x, W, dtw, dtb);
    k_scan1    <<<dim3(NC, KK), 96>>>(Al);
    k_scan2    <<<48, 128>>>(Al);
    k_scan3    <<<dim3(NC, KK), 96>>>(Al, Ds);
    k_final    <<<LL, 96>>>(lnw, lnb, out);
}

// round 3
// speedup vs baseline: 1.6560x; 1.6560x over previous
#include <cuda_runtime.h>
#include <math.h>

#define DD 96
#define LL 9216
#define KK 4
#define NN 16
#define RR 6
#define CC 38
#define LC 16
#define NC 576   // LL/LC
#define KD 384   // KK*DD

// scratch (no allocations allowed)
__device__ float  g_xT[DD*LL];          // transposed image per d
__device__ float  g_BC[KK*LL*32];       // (k,l,[B0..15,C0..15])
__device__ float2 g_dx[KK*LL*DD];       // (k,l,d) -> (delta, x)
__device__ float  g_Sd[NC*KD];          // per-chunk sum of delta
__device__ float  g_H [NC*KD*NN];       // per-chunk h (pass1) then h_in (pass2)
__device__ float  g_y [KK*LL*DD];       // (k,l,d) scan output

// ---------------------------------------------------------------------------
// Kernel T: per-d HW transpose of x
// ---------------------------------------------------------------------------
__global__ void k_transpose(const float* __restrict__ x){
    __shared__ float tile[32][33];
    int d  = blockIdx.z;
    int h0 = blockIdx.x*32, w0 = blockIdx.y*32;
    int tx = threadIdx.x,  ty = threadIdx.y;
    const float* xp = x    + (size_t)d*LL;
    float*       op = g_xT + (size_t)d*LL;
    #pragma unroll
    for (int i=0;i<4;i++) tile[ty+8*i][tx] = xp[(h0+ty+8*i)*96 + w0+tx];
    __syncthreads();
    #pragma unroll
    for (int i=0;i<4;i++) op[(w0+ty+8*i)*96 + h0+tx] = tile[tx][ty+8*i];
}

// ---------------------------------------------------------------------------
// Kernel A: projections. Block = (32 l-values, one k).
// ---------------------------------------------------------------------------
__global__ __launch_bounds__(256) void k_proj(
    const float* __restrict__ x,  const float* __restrict__ W,
    const float* __restrict__ dtw,const float* __restrict__ dtb)
{
    __shared__ float xs_s [96*33];
    __shared__ float Wt_s [96*40];
    __shared__ float dbl_s[40*33];
    __shared__ float Wdt_s[96*6];
    __shared__ float bias_s[96];

    int k   = blockIdx.y;
    int l0  = blockIdx.x*32;
    int tid = threadIdx.x;
    const float* src = (k & 1) ? g_xT : x;

    for (int idx=tid; idx<96*32; idx+=256){
        int d = idx>>5, li = idx&31;
        int l = l0+li;
        int ls = (k<2) ? l : (LL-1-l);
        xs_s[d*33+li] = src[(size_t)d*LL + ls];
    }
    for (int idx=tid; idx<CC*96; idx+=256){
        int c = idx/96, d = idx - c*96;
        Wt_s[d*40+c] = W[(k*CC+c)*96 + d];
    }
    for (int idx=tid; idx<96*6; idx+=256) Wdt_s[idx] = dtw[k*576 + idx];
    if (tid < 96) bias_s[tid] = dtb[k*96 + tid];
    __syncthreads();

    int lane = tid & 31, wrp = tid >> 5;
    #pragma unroll
    for (int qq=0; qq<2; qq++){
        int q = wrp + qq*8;
        if (q < 10){
            int c0 = q*4;
            float ax=0.f, ay=0.f, az=0.f, aw=0.f;
            for (int d=0; d<96; d++){
                float  xv = xs_s[d*33+lane];
                float4 wv = *(const float4*)&Wt_s[d*40+c0];
                ax = fmaf(wv.x, xv, ax); ay = fmaf(wv.y, xv, ay);
                az = fmaf(wv.z, xv, az); aw = fmaf(wv.w, xv, aw);
            }
            dbl_s[(c0+0)*33+lane] = ax;
            dbl_s[(c0+1)*33+lane] = ay;
            dbl_s[(c0+2)*33+lane] = az;
            dbl_s[(c0+3)*33+lane] = aw;
        }
    }
    __syncthreads();

    for (int idx=tid; idx<32*32; idx+=256){
        int li = idx>>5, j = idx&31;
        g_BC[((size_t)k*LL + l0+li)*32 + j] = dbl_s[(6+j)*33 + li];
    }
    for (int idx=tid; idx<96*32; idx+=256){
        int d = idx%96, li = idx/96;
        float acc = bias_s[d];
        #pragma unroll
        for (int r=0; r<6; r++) acc = fmaf(dbl_s[r*33+li], Wdt_s[d*6+r], acc);
        float sp = (acc > 20.f) ? acc : log1pf(__expf(acc));
        g_dx[((size_t)k*LL + l0+li)*96 + d] = make_float2(sp, xs_s[d*33+li]);
    }
}

// ---------------------------------------------------------------------------
// Pass 1: per-chunk local scan (h_in = 0). Block = (chunk, k), thread = d.
// ---------------------------------------------------------------------------
__global__ __launch_bounds__(96) void k_scan1(const float* __restrict__ A_logs){
    __shared__ float BC_s[LC*32];
    int k = blockIdx.y, ch = blockIdx.x;
    int c0 = ch*LC;
    int d  = threadIdx.x;
    for (int idx=d; idx<LC*32; idx+=96)
        BC_s[idx] = g_BC[((size_t)k*LL + c0)*32 + idx];
    __syncthreads();

    float Aa[NN];
    #pragma unroll
    for (int n=0;n<NN;n++) Aa[n] = -__expf(A_logs[(k*96+d)*NN + n]);
    float h[NN];
    #pragma unroll
    for (int n=0;n<NN;n++) h[n] = 0.f;
    float sd = 0.f;

    const float2* dxp = g_dx + ((size_t)k*LL + c0)*96 + d;
    #pragma unroll 2
    for (int li=0; li<LC; li++){
        float2 dv = dxp[(size_t)li*96];
        float delta = dv.x;
        float du    = dv.x*dv.y;
        sd += delta;
        const float4* bp = (const float4*)&BC_s[li*32];
        float4 b0=bp[0], b1=bp[1], b2=bp[2], b3=bp[3];
        float Bv[16] = {b0.x,b0.y,b0.z,b0.w, b1.x,b1.y,b1.z,b1.w,
                        b2.x,b2.y,b2.z,b2.w, b3.x,b3.y,b3.z,b3.w};
        #pragma unroll
        for (int n=0;n<NN;n++)
            h[n] = fmaf(h[n], __expf(delta*Aa[n]), du*Bv[n]);
    }
    int base = ch*KD + k*96 + d;
    g_Sd[base] = sd;
    float4* hp = (float4*)&g_H[(size_t)base*16];
    hp[0] = make_float4(h[0] ,h[1] ,h[2] ,h[3] );
    hp[1] = make_float4(h[4] ,h[5] ,h[6] ,h[7] );
    hp[2] = make_float4(h[8] ,h[9] ,h[10],h[11]);
    hp[3] = make_float4(h[12],h[13],h[14],h[15]);
}

// ---------------------------------------------------------------------------
// Pass 2: parallel chunk-combine. One block per (k,d) sequence.
// 512 threads = 16 warps; warp n owns state n; lane g owns 18 chunks.
// Affine pair per chunk: h_out = P*h_in + q, P = exp(A_n * Sd[ch]), q = local h.
// Writes each chunk's INCOMING state back into g_H.
// ---------------------------------------------------------------------------
#define CPT 18   // chunks per thread: 32*18 = 576 = NC
__global__ __launch_bounds__(512) void k_scan2(const float* __restrict__ A_logs){
    __shared__ float sH [NC*17];   // [ch][n] padded stride 17
    __shared__ float sSd[NC];

    int kd  = blockIdx.x;           // 0..383
    int tid = threadIdx.x;

    // coalesced stage-in of H slab
    for (int idx=tid; idx<NC*16; idx+=512){
        int ch = idx>>4, n = idx&15;
        sH[ch*17+n] = g_H[(size_t)ch*(KD*16) + kd*16 + n];
    }
    for (int ch=tid; ch<NC; ch+=512)
        sSd[ch] = g_Sd[ch*KD + kd];
    __syncthreads();

    int n = tid >> 5;        // warp id = state index
    int g = tid & 31;        // lane  = chunk group
    float Av = -__expf(A_logs[kd*16 + n]);
    int ch0 = g*CPT;

    // pass A: local aggregate over my 18 chunks
    float Pv[CPT];
    float a = 1.f, b = 0.f;
    #pragma unroll
    for (int j=0; j<CPT; j++){
        float P = __expf(Av * sSd[ch0+j]);
        Pv[j] = P;
        float q = sH[(ch0+j)*17 + n];
        b = fmaf(P, b, q);
        a = a * P;
    }

    // inclusive warp scan of affine pairs (compose: newer applied after older)
    #pragma unroll
    for (int o=1; o<32; o<<=1){
        float ap = __shfl_up_sync(0xffffffffu, a, o);
        float bp = __shfl_up_sync(0xffffffffu, b, o);
        if (g >= o){
            b = fmaf(a, bp, b);
            a = a * ap;
        }
    }
    // exclusive: incoming h at start of my range = b of previous lane (h0=0 => h=b)
    float bex = __shfl_up_sync(0xffffffffu, b, 1);
    float h = (g == 0) ? 0.f : bex;

    // pass B: replay, writing incoming state per chunk
    #pragma unroll
    for (int j=0; j<CPT; j++){
        float q = sH[(ch0+j)*17 + n];
        sH[(ch0+j)*17 + n] = h;
        h = fmaf(Pv[j], h, q);
    }
    __syncthreads();

    // coalesced stage-out
    for (int idx=tid; idx<NC*16; idx+=512){
        int ch = idx>>4, nn = idx&15;
        g_H[(size_t)ch*(KD*16) + kd*16 + nn] = sH[ch*17+nn];
    }
}

// ---------------------------------------------------------------------------
// Pass 3: replay chunk with correct h_in, emit y = sum_n h_n*C_n + x*Ds.
// ---------------------------------------------------------------------------
__global__ __launch_bounds__(96) void k_scan3(const float* __restrict__ A_logs,
                                              const float* __restrict__ Ds){
    __shared__ float BC_s[LC*32];
    int k = blockIdx.y, ch = blockIdx.x;
    int c0 = ch*LC;
    int d  = threadIdx.x;
    for (int idx=d; idx<LC*32; idx+=96)
        BC_s[idx] = g_BC[((size_t)k*LL + c0)*32 + idx];
    __syncthreads();

    float Aa[NN];
    #pragma unroll
    for (int n=0;n<NN;n++) Aa[n] = -__expf(A_logs[(k*96+d)*NN + n]);

    int base = ch*KD + k*96 + d;
    const float4* hp = (const float4*)&g_H[(size_t)base*16];
    float4 h0v=hp[0], h1v=hp[1], h2v=hp[2], h3v=hp[3];
    float h[16] = {h0v.x,h0v.y,h0v.z,h0v.w, h1v.x,h1v.y,h1v.z,h1v.w,
                   h2v.x,h2v.y,h2v.z,h2v.w, h3v.x,h3v.y,h3v.z,h3v.w};
    float Dsv = Ds[k*96 + d];

    const float2* dxp = g_dx + ((size_t)k*LL + c0)*96 + d;
    float*        yp  = g_y  + ((size_t)k*LL + c0)*96 + d;
    #pragma unroll 2
    for (int li=0; li<LC; li++){
        float2 dv = dxp[(size_t)li*96];
        float delta = dv.x, xv = dv.y;
        float du = delta*xv;
        const float4* bp = (const float4*)&BC_s[li*32];
        float4 b0=bp[0], b1=bp[1], b2=bp[2], b3=bp[3];
        float4 q0=bp[4], q1=bp[5], q2=bp[6], q3=bp[7];
        float Bv[16] = {b0.x,b0.y,b0.z,b0.w, b1.x,b1.y,b1.z,b1.w,
                        b2.x,b2.y,b2.z,b2.w, b3.x,b3.y,b3.z,b3.w};
        float Cv[16] = {q0.x,q0.y,q0.z,q0.w, q1.x,q1.y,q1.z,q1.w,
                        q2.x,q2.y,q2.z,q2.w, q3.x,q3.y,q3.z,q3.w};
        float y = xv*Dsv;
        #pragma unroll
        for (int n=0;n<NN;n++){
            h[n] = fmaf(h[n], __expf(delta*Aa[n]), du*Bv[n]);
            y    = fmaf(h[n], Cv[n], y);
        }
        yp[(size_t)li*96] = y;
    }
}

// ---------------------------------------------------------------------------
// Final: combine 4 directions (reverse/transpose-back), layernorm over D=96.
// ---------------------------------------------------------------------------
__global__ __launch_bounds__(96) void k_final(const float* __restrict__ lnw,
                                              const float* __restrict__ lnb,
                                              float* __restrict__ out){
    int l  = blockIdx.x;
    int d  = threadIdx.x;
    int hh = l/96, ww = l - hh*96;
    int lt = ww*96 + hh;
    float v = g_y[(size_t)(0*LL + l)           *96 + d]
            + g_y[(size_t)(2*LL + (LL-1-l))    *96 + d]
            + g_y[(size_t)(1*LL + lt)          *96 + d]
            + g_y[(size_t)(3*LL + (LL-1-lt))   *96 + d];
    float s = v, ss = v*v;
    #pragma unroll
    for (int o=16;o>0;o>>=1){
        s  += __shfl_xor_sync(0xffffffffu, s,  o);
        ss += __shfl_xor_sync(0xffffffffu, ss, o);
    }
    __shared__ float rs[3], rss[3];
    int wid = d>>5;
    if ((d&31)==0){ rs[wid]=s; rss[wid]=ss; }
    __syncthreads();
    float tot  = rs[0]+rs[1]+rs[2];
    float tot2 = rss[0]+rss[1]+rss[2];
    float mu  = tot*(1.f/96.f);
    float var = fmaxf(tot2*(1.f/96.f) - mu*mu, 0.f);
    float r   = rsqrtf(var + 1e-5f);
    out[(size_t)l*96 + d] = (v-mu)*r*lnw[d] + lnb[d];
}

// ---------------------------------------------------------------------------
extern "C" void kernel_launch(void* const* d_in, const int* in_sizes, int n_in,
                              void* d_out, int out_size)
{
    const float* x   = (const float*)d_in[0];
    const float* W   = (const float*)d_in[1];
    const float* dtw = (const float*)d_in[2];
    const float* dtb = (const float*)d_in[3];
    const float* Al  = (const float*)d_in[4];
    const float* Ds  = (const float*)d_in[5];
    const float* lnw = (const float*)d_in[6];
    const float* lnb = (const float*)d_in[7];
    float* out = (float*)d_out;

    k_transpose<<<dim3(3,3,96), dim3(32,8)>>>(x);
    k_proj     <<<dim3(LL/32, KK), 256>>>(x, W, dtw, dtb);
    k_scan1    <<<dim3(NC, KK), 96>>>(Al);
    k_scan2    <<<KD, 512>>>(Al);
    k_scan3    <<<dim3(NC, KK), 96>>>(Al, Ds);
    k_final    <<<LL, 96>>>(lnw, lnb, out);
}

// round 5
// speedup vs baseline: 1.7374x; 1.0492x over previous
#include <cuda_runtime.h>
#include <math.h>

#define DD 96
#define LL 9216
#define KK 4
#define NN 16
#define RR 6
#define CC 38
#define LC 16
#define NC 576   // LL/LC
#define KD 384   // KK*DD

// scratch (no allocations allowed)
__device__ float  g_xT[DD*LL];          // transposed image per d
__device__ float  g_BC[KK*LL*32];       // (k,l,[B0..15,C0..15])
__device__ float2 g_dx[KK*LL*DD];       // (k,l,d) -> (delta, x)
__device__ float  g_Sd[KD*NC];          // [kd][ch] per-chunk sum of delta
__device__ float  g_H [KD*NC*NN];       // [kd][ch][n] chunk h (pass1) then h_in (pass2)
__device__ float  g_y [KK*LL*DD];       // 4 planes, all aligned to output index l

// ---------------------------------------------------------------------------
// Kernel T: per-d HW transpose of x
// ---------------------------------------------------------------------------
__global__ void k_transpose(const float* __restrict__ x){
    __shared__ float tile[32][33];
    int d  = blockIdx.z;
    int h0 = blockIdx.x*32, w0 = blockIdx.y*32;
    int tx = threadIdx.x,  ty = threadIdx.y;
    const float* xp = x    + (size_t)d*LL;
    float*       op = g_xT + (size_t)d*LL;
    #pragma unroll
    for (int i=0;i<4;i++) tile[ty+8*i][tx] = xp[(h0+ty+8*i)*96 + w0+tx];
    __syncthreads();
    #pragma unroll
    for (int i=0;i<4;i++) op[(w0+ty+8*i)*96 + h0+tx] = tile[tx][ty+8*i];
}

// ---------------------------------------------------------------------------
// Kernel A: projections. Block = (32 l-values, one k).
// ---------------------------------------------------------------------------
__global__ __launch_bounds__(256) void k_proj(
    const float* __restrict__ x,  const float* __restrict__ W,
    const float* __restrict__ dtw,const float* __restrict__ dtb)
{
    __shared__ float xs_s [96*33];
    __shared__ float Wt_s [96*40];
    __shared__ float dbl_s[40*33];
    __shared__ float Wdt_s[96*6];
    __shared__ float bias_s[96];

    int k   = blockIdx.y;
    int l0  = blockIdx.x*32;
    int tid = threadIdx.x;
    const float* src = (k & 1) ? g_xT : x;

    for (int idx=tid; idx<96*32; idx+=256){
        int d = idx>>5, li = idx&31;
        int l = l0+li;
        int ls = (k<2) ? l : (LL-1-l);
        xs_s[d*33+li] = src[(size_t)d*LL + ls];
    }
    for (int idx=tid; idx<CC*96; idx+=256){
        int c = idx/96, d = idx - c*96;
        Wt_s[d*40+c] = W[(k*CC+c)*96 + d];
    }
    for (int idx=tid; idx<96*6; idx+=256) Wdt_s[idx] = dtw[k*576 + idx];
    if (tid < 96) bias_s[tid] = dtb[k*96 + tid];
    __syncthreads();

    int lane = tid & 31, wrp = tid >> 5;
    #pragma unroll
    for (int qq=0; qq<2; qq++){
        int q = wrp + qq*8;
        if (q < 10){
            int c0 = q*4;
            float ax=0.f, ay=0.f, az=0.f, aw=0.f;
            for (int d=0; d<96; d++){
                float  xv = xs_s[d*33+lane];
                float4 wv = *(const float4*)&Wt_s[d*40+c0];
                ax = fmaf(wv.x, xv, ax); ay = fmaf(wv.y, xv, ay);
                az = fmaf(wv.z, xv, az); aw = fmaf(wv.w, xv, aw);
            }
            dbl_s[(c0+0)*33+lane] = ax;
            dbl_s[(c0+1)*33+lane] = ay;
            dbl_s[(c0+2)*33+lane] = az;
            dbl_s[(c0+3)*33+lane] = aw;
        }
    }
    __syncthreads();

    for (int idx=tid; idx<32*32; idx+=256){
        int li = idx>>5, j = idx&31;
        g_BC[((size_t)k*LL + l0+li)*32 + j] = dbl_s[(6+j)*33 + li];
    }
    for (int idx=tid; idx<96*32; idx+=256){
        int d = idx%96, li = idx/96;
        float acc = bias_s[d];
        #pragma unroll
        for (int r=0; r<6; r++) acc = fmaf(dbl_s[r*33+li], Wdt_s[d*6+r], acc);
        float sp = (acc > 20.f) ? acc : log1pf(__expf(acc));
        g_dx[((size_t)k*LL + l0+li)*96 + d] = make_float2(sp, xs_s[d*33+li]);
    }
}

// ---------------------------------------------------------------------------
// Pass 1: per-chunk local scan (h_in = 0). Block = (chunk, k), thread = d.
// Writes H in [kd][ch][n] layout, Sd in [kd][ch].
// ---------------------------------------------------------------------------
__global__ __launch_bounds__(96) void k_scan1(const float* __restrict__ A_logs){
    __shared__ float BC_s[LC*32];
    int k = blockIdx.y, ch = blockIdx.x;
    int c0 = ch*LC;
    int d  = threadIdx.x;
    for (int idx=d; idx<LC*32; idx+=96)
        BC_s[idx] = g_BC[((size_t)k*LL + c0)*32 + idx];
    __syncthreads();

    float Aa[NN];
    #pragma unroll
    for (int n=0;n<NN;n++) Aa[n] = -__expf(A_logs[(k*96+d)*NN + n]);
    float h[NN];
    #pragma unroll
    for (int n=0;n<NN;n++) h[n] = 0.f;
    float sd = 0.f;

    const float2* dxp = g_dx + ((size_t)k*LL + c0)*96 + d;
    #pragma unroll 2
    for (int li=0; li<LC; li++){
        float2 dv = dxp[(size_t)li*96];
        float delta = dv.x;
        float du    = dv.x*dv.y;
        sd += delta;
        const float4* bp = (const float4*)&BC_s[li*32];
        float4 b0=bp[0], b1=bp[1], b2=bp[2], b3=bp[3];
        float Bv[16] = {b0.x,b0.y,b0.z,b0.w, b1.x,b1.y,b1.z,b1.w,
                        b2.x,b2.y,b2.z,b2.w, b3.x,b3.y,b3.z,b3.w};
        #pragma unroll
        for (int n=0;n<NN;n++)
            h[n] = fmaf(h[n], __expf(delta*Aa[n]), du*Bv[n]);
    }
    int kd = k*96 + d;
    g_Sd[(size_t)kd*NC + ch] = sd;
    float4* hp = (float4*)&g_H[((size_t)kd*NC + ch)*16];
    hp[0] = make_float4(h[0] ,h[1] ,h[2] ,h[3] );
    hp[1] = make_float4(h[4] ,h[5] ,h[6] ,h[7] );
    hp[2] = make_float4(h[8] ,h[9] ,h[10],h[11]);
    hp[3] = make_float4(h[12],h[13],h[14],h[15]);
}

// ---------------------------------------------------------------------------
// Pass 2: parallel chunk-combine. One block per (k,d) sequence.
// 512 threads = 16 warps; warp n owns state n; lane g owns 18 chunks.
// [kd][ch][n] layout -> fully contiguous float4 stage-in/out.
// ---------------------------------------------------------------------------
#define CPT 18   // chunks per thread: 32*18 = 576 = NC
__global__ __launch_bounds__(512) void k_scan2(const float* __restrict__ A_logs){
    __shared__ float sH [NC*17];   // [ch][n] padded stride 17
    __shared__ float sSd[NC];

    int kd  = blockIdx.x;           // 0..383
    int tid = threadIdx.x;

    // contiguous float4 stage-in of the whole H slab (36.9 KB)
    const float4* src4 = (const float4*)(g_H + (size_t)kd*NC*16);
    for (int i=tid; i<NC*4; i+=512){
        float4 v = src4[i];
        int e = i*4; int ch = e>>4, n = e&15;
        float* p = &sH[ch*17+n];
        p[0]=v.x; p[1]=v.y; p[2]=v.z; p[3]=v.w;
    }
    const float4* sd4 = (const float4*)(g_Sd + (size_t)kd*NC);
    for (int i=tid; i<NC/4; i+=512){
        float4 v = sd4[i];
        sSd[i*4+0]=v.x; sSd[i*4+1]=v.y; sSd[i*4+2]=v.z; sSd[i*4+3]=v.w;
    }
    __syncthreads();

    int n = tid >> 5;        // warp id = state index
    int g = tid & 31;        // lane  = chunk group
    float Av = -__expf(A_logs[kd*16 + n]);
    int ch0 = g*CPT;

    // pass A: local aggregate over my 18 chunks
    float Pv[CPT];
    float a = 1.f, b = 0.f;
    #pragma unroll
    for (int j=0; j<CPT; j++){
        float P = __expf(Av * sSd[ch0+j]);
        Pv[j] = P;
        float q = sH[(ch0+j)*17 + n];
        b = fmaf(P, b, q);
        a = a * P;
    }

    // inclusive warp scan of affine pairs
    #pragma unroll
    for (int o=1; o<32; o<<=1){
        float ap = __shfl_up_sync(0xffffffffu, a, o);
        float bp = __shfl_up_sync(0xffffffffu, b, o);
        if (g >= o){
            b = fmaf(a, bp, b);
            a = a * ap;
        }
    }
    float bex = __shfl_up_sync(0xffffffffu, b, 1);
    float h = (g == 0) ? 0.f : bex;

    // pass B: replay, writing incoming state per chunk
    #pragma unroll
    for (int j=0; j<CPT; j++){
        float q = sH[(ch0+j)*17 + n];
        sH[(ch0+j)*17 + n] = h;
        h = fmaf(Pv[j], h, q);
    }
    __syncthreads();

    // contiguous float4 stage-out
    float4* dst4 = (float4*)(g_H + (size_t)kd*NC*16);
    for (int i=tid; i<NC*4; i+=512){
        int e = i*4; int ch = e>>4, nn = e&15;
        const float* p = &sH[ch*17+nn];
        dst4[i] = make_float4(p[0], p[1], p[2], p[3]);
    }
}

// ---------------------------------------------------------------------------
// Pass 3: replay chunk with correct h_in, emit y. Writes each k's plane
// pre-reversed / pre-transposed so k_final reads all planes at index l.
// ---------------------------------------------------------------------------
__global__ __launch_bounds__(96) void k_scan3(const float* __restrict__ A_logs,
                                              const float* __restrict__ Ds){
    __shared__ float BC_s[LC*32];
    int k = blockIdx.y, ch = blockIdx.x;
    int c0 = ch*LC;
    int d  = threadIdx.x;
    for (int idx=d; idx<LC*32; idx+=96)
        BC_s[idx] = g_BC[((size_t)k*LL + c0)*32 + idx];
    __syncthreads();

    float Aa[NN];
    #pragma unroll
    for (int n=0;n<NN;n++) Aa[n] = -__expf(A_logs[(k*96+d)*NN + n]);

    int kd = k*96 + d;
    const float4* hp = (const float4*)&g_H[((size_t)kd*NC + ch)*16];
    float4 h0v=hp[0], h1v=hp[1], h2v=hp[2], h3v=hp[3];
    float h[16] = {h0v.x,h0v.y,h0v.z,h0v.w, h1v.x,h1v.y,h1v.z,h1v.w,
                   h2v.x,h2v.y,h2v.z,h2v.w, h3v.x,h3v.y,h3v.z,h3v.w};
    float Dsv = Ds[kd];

    const float2* dxp = g_dx + ((size_t)k*LL + c0)*96 + d;
    float*        pl  = g_y  + (size_t)k*LL*96;
    #pragma unroll 2
    for (int li=0; li<LC; li++){
        float2 dv = dxp[(size_t)li*96];
        float delta = dv.x, xv = dv.y;
        float du = delta*xv;
        const float4* bp = (const float4*)&BC_s[li*32];
        float4 b0=bp[0], b1=bp[1], b2=bp[2], b3=bp[3];
        float4 q0=bp[4], q1=bp[5], q2=bp[6], q3=bp[7];
        float Bv[16] = {b0.x,b0.y,b0.z,b0.w, b1.x,b1.y,b1.z,b1.w,
                        b2.x,b2.y,b2.z,b2.w, b3.x,b3.y,b3.z,b3.w};
        float Cv[16] = {q0.x,q0.y,q0.z,q0.w, q1.x,q1.y,q1.z,q1.w,
                        q2.x,q2.y,q2.z,q2.w, q3.x,q3.y,q3.z,q3.w};
        float y = xv*Dsv;
        #pragma unroll
        for (int n=0;n<NN;n++){
            h[n] = fmaf(h[n], __expf(delta*Aa[n]), du*Bv[n]);
            y    = fmaf(h[n], Cv[n], y);
        }
        int l = c0 + li;
        int slot;
        if      (k == 0) slot = l;
        else if (k == 2) slot = LL-1-l;
        else if (k == 1){ int r = l/96;  slot = (l - r*96)*96 + r; }
        else            { int lm = LL-1-l; int r = lm/96; slot = (lm - r*96)*96 + r; }
        pl[(size_t)slot*96 + d] = y;
    }
}

// ---------------------------------------------------------------------------
// Final: sum 4 pre-aligned planes, layernorm over D=96.
// 384 threads = 4 l-groups of 3 warps.
// ---------------------------------------------------------------------------
__global__ __launch_bounds__(384) void k_final(const float* __restrict__ lnw,
                                               const float* __restrict__ lnb,
                                               float* __restrict__ out){
    int t   = threadIdx.x;
    int grp = t / 96;
    int d   = t - grp*96;
    int l   = blockIdx.x*4 + grp;
    size_t base = (size_t)l*96 + d;
    float v = g_y[base]
            + g_y[(size_t)1*LL*96 + base]
            + g_y[(size_t)2*LL*96 + base]
            + g_y[(size_t)3*LL*96 + base];
    float s = v, ss = v*v;
    #pragma unroll
    for (int o=16;o>0;o>>=1){
        s  += __shfl_xor_sync(0xffffffffu, s,  o);
        ss += __shfl_xor_sync(0xffffffffu, ss, o);
    }
    __shared__ float rs[4][3], rss[4][3];
    int wig = d >> 5;
    if ((d&31)==0){ rs[grp][wig]=s; rss[grp][wig]=ss; }
    __syncthreads();
    float tot  = rs[grp][0]+rs[grp][1]+rs[grp][2];
    float tot2 = rss[grp][0]+rss[grp][1]+rss[grp][2];
    float mu  = tot*(1.f/96.f);
    float var = fmaxf(tot2*(1.f/96.f) - mu*mu, 0.f);
    float r   = rsqrtf(var + 1e-5f);
    out[base] = (v-mu)*r*lnw[d] + lnb[d];
}

// ---------------------------------------------------------------------------
extern "C" void kernel_launch(void* const* d_in, const int* in_sizes, int n_in,
                              void* d_out, int out_size)
{
    const float* x   = (const float*)d_in[0];
    const float* W   = (const float*)d_in[1];
    const float* dtw = (const float*)d_in[2];
    const float* dtb = (const float*)d_in[3];
    const float* Al  = (const float*)d_in[4];
    const float* Ds  = (const float*)d_in[5];
    const float* lnw = (const float*)d_in[6];
    const float* lnb = (const float*)d_in[7];
    float* out = (float*)d_out;

    k_transpose<<<dim3(3,3,96), dim3(32,8)>>>(x);
    k_proj     <<<dim3(LL/32, KK), 256>>>(x, W, dtw, dtb);
    k_scan1    <<<dim3(NC, KK), 96>>>(Al);
    k_scan2    <<<KD, 512>>>(Al);
    k_scan3    <<<dim3(NC, KK), 96>>>(Al, Ds);
    k_final    <<<LL/4, 384>>>(lnw, lnb, out);
}

// round 6
// speedup vs baseline: 1.7412x; 1.0022x over previous
#include <cuda_runtime.h>
#include <math.h>

#define DD 96
#define LL 9216
#define KK 4
#define NN 16
#define RR 6
#define CC 38
#define LC 16
#define NC 576   // LL/LC
#define KD 384   // KK*DD

// scratch (no allocations allowed)
__device__ float  g_xT[DD*LL];          // transposed image per d
__device__ float  g_BC[KK*LL*32];       // (k,l,[B0..15,C0..15])
__device__ float2 g_dx[KK*LL*DD];       // (k,l,d) -> (delta, x)
__device__ float  g_Sd[KD*NC];          // [kd][ch] per-chunk sum of delta
__device__ float  g_H [KD*NC*NN];       // [kd][ch][n] chunk h (pass1) then h_in (pass2)
__device__ float  g_y [KK*LL*DD];       // 4 planes, all aligned to output index l

// ---------------------------------------------------------------------------
// Kernel T: per-d HW transpose of x
// ---------------------------------------------------------------------------
__global__ void k_transpose(const float* __restrict__ x){
    __shared__ float tile[32][33];
    int d  = blockIdx.z;
    int h0 = blockIdx.x*32, w0 = blockIdx.y*32;
    int tx = threadIdx.x,  ty = threadIdx.y;
    const float* xp = x    + (size_t)d*LL;
    float*       op = g_xT + (size_t)d*LL;
    #pragma unroll
    for (int i=0;i<4;i++) tile[ty+8*i][tx] = xp[(h0+ty+8*i)*96 + w0+tx];
    __syncthreads();
    #pragma unroll
    for (int i=0;i<4;i++) op[(w0+ty+8*i)*96 + h0+tx] = tile[tx][ty+8*i];
}

// ---------------------------------------------------------------------------
// Kernel A (fused): projections + chunk-local scan (old k_scan1).
// Block = (32 l-values = 2 chunks, one k).
// After the GEMM, threads 0..191 run the local scan for the block's 2 chunks
// straight out of shared memory, writing Sd and H in [kd][ch][n] layout.
// ---------------------------------------------------------------------------
__global__ __launch_bounds__(256) void k_proj(
    const float* __restrict__ x,  const float* __restrict__ W,
    const float* __restrict__ dtw,const float* __restrict__ dtb,
    const float* __restrict__ A_logs)
{
    __shared__ float xs_s [96*33];
    __shared__ float Wt_s [96*40];   // reused as delta_s (96*33) after GEMM
    __shared__ float dbl_s[40*33];
    __shared__ float Wdt_s[96*6];
    __shared__ float bias_s[96];

    int k   = blockIdx.y;
    int l0  = blockIdx.x*32;
    int tid = threadIdx.x;
    const float* src = (k & 1) ? g_xT : x;

    for (int idx=tid; idx<96*32; idx+=256){
        int d = idx>>5, li = idx&31;
        int l = l0+li;
        int ls = (k<2) ? l : (LL-1-l);
        xs_s[d*33+li] = src[(size_t)d*LL + ls];
    }
    for (int idx=tid; idx<CC*96; idx+=256){
        int c = idx/96, d = idx - c*96;
        Wt_s[d*40+c] = W[(k*CC+c)*96 + d];
    }
    for (int idx=tid; idx<96*6; idx+=256) Wdt_s[idx] = dtw[k*576 + idx];
    if (tid < 96) bias_s[tid] = dtb[k*96 + tid];
    __syncthreads();

    int lane = tid & 31, wrp = tid >> 5;
    #pragma unroll
    for (int qq=0; qq<2; qq++){
        int q = wrp + qq*8;
        if (q < 10){
            int c0 = q*4;
            float ax=0.f, ay=0.f, az=0.f, aw=0.f;
            for (int d=0; d<96; d++){
                float  xv = xs_s[d*33+lane];
                float4 wv = *(const float4*)&Wt_s[d*40+c0];
                ax = fmaf(wv.x, xv, ax); ay = fmaf(wv.y, xv, ay);
                az = fmaf(wv.z, xv, az); aw = fmaf(wv.w, xv, aw);
            }
            dbl_s[(c0+0)*33+lane] = ax;
            dbl_s[(c0+1)*33+lane] = ay;
            dbl_s[(c0+2)*33+lane] = az;
            dbl_s[(c0+3)*33+lane] = aw;
        }
    }
    __syncthreads();   // GEMM done; Wt_s is now dead -> reuse as delta_s

    float* delta_s = Wt_s;   // [d*33 + li]

    // B,C out
    for (int idx=tid; idx<32*32; idx+=256){
        int li = idx>>5, j = idx&31;
        g_BC[((size_t)k*LL + l0+li)*32 + j] = dbl_s[(6+j)*33 + li];
    }
    // delta + x out (also keep delta in smem for the fused scan)
    for (int idx=tid; idx<96*32; idx+=256){
        int d = idx%96, li = idx/96;
        float acc = bias_s[d];
        #pragma unroll
        for (int r=0; r<6; r++) acc = fmaf(dbl_s[r*33+li], Wdt_s[d*6+r], acc);
        float sp = (acc > 20.f) ? acc : log1pf(__expf(acc));
        delta_s[d*33+li] = sp;
        g_dx[((size_t)k*LL + l0+li)*96 + d] = make_float2(sp, xs_s[d*33+li]);
    }
    __syncthreads();

    // fused chunk-local scan: 2 chunks of LC=16, threads 0..191
    if (tid < 192){
        int sub = tid / 96;          // which chunk within block
        int d   = tid - sub*96;
        int kd  = k*96 + d;
        int ch  = blockIdx.x*2 + sub;
        int lb  = sub*16;

        float Aa[NN];
        #pragma unroll
        for (int n=0;n<NN;n++) Aa[n] = -__expf(A_logs[kd*NN + n]);
        float h[NN];
        #pragma unroll
        for (int n=0;n<NN;n++) h[n] = 0.f;
        float sd = 0.f;

        #pragma unroll 2
        for (int i=0; i<LC; i++){
            int li = lb + i;
            float delta = delta_s[d*33+li];
            float du    = delta * xs_s[d*33+li];
            sd += delta;
            #pragma unroll
            for (int n=0;n<NN;n++)
                h[n] = fmaf(h[n], __expf(delta*Aa[n]), du*dbl_s[(6+n)*33+li]);
        }
        g_Sd[(size_t)kd*NC + ch] = sd;
        float4* hp = (float4*)&g_H[((size_t)kd*NC + ch)*16];
        hp[0] = make_float4(h[0] ,h[1] ,h[2] ,h[3] );
        hp[1] = make_float4(h[4] ,h[5] ,h[6] ,h[7] );
        hp[2] = make_float4(h[8] ,h[9] ,h[10],h[11]);
        hp[3] = make_float4(h[12],h[13],h[14],h[15]);
    }
}

// ---------------------------------------------------------------------------
// Pass 2: parallel chunk-combine. One block per (k,d) sequence.
// ---------------------------------------------------------------------------
#define CPT 18   // chunks per thread: 32*18 = 576 = NC
__global__ __launch_bounds__(512) void k_scan2(const float* __restrict__ A_logs){
    __shared__ float sH [NC*17];   // [ch][n] padded stride 17
    __shared__ float sSd[NC];

    int kd  = blockIdx.x;           // 0..383
    int tid = threadIdx.x;

    const float4* src4 = (const float4*)(g_H + (size_t)kd*NC*16);
    for (int i=tid; i<NC*4; i+=512){
        float4 v = src4[i];
        int e = i*4; int ch = e>>4, n = e&15;
        float* p = &sH[ch*17+n];
        p[0]=v.x; p[1]=v.y; p[2]=v.z; p[3]=v.w;
    }
    const float4* sd4 = (const float4*)(g_Sd + (size_t)kd*NC);
    for (int i=tid; i<NC/4; i+=512){
        float4 v = sd4[i];
        sSd[i*4+0]=v.x; sSd[i*4+1]=v.y; sSd[i*4+2]=v.z; sSd[i*4+3]=v.w;
    }
    __syncthreads();

    int n = tid >> 5;        // warp id = state index
    int g = tid & 31;        // lane  = chunk group
    float Av = -__expf(A_logs[kd*16 + n]);
    int ch0 = g*CPT;

    float Pv[CPT];
    float a = 1.f, b = 0.f;
    #pragma unroll
    for (int j=0; j<CPT; j++){
        float P = __expf(Av * sSd[ch0+j]);
        Pv[j] = P;
        float q = sH[(ch0+j)*17 + n];
        b = fmaf(P, b, q);
        a = a * P;
    }

    #pragma unroll
    for (int o=1; o<32; o<<=1){
        float ap = __shfl_up_sync(0xffffffffu, a, o);
        float bp = __shfl_up_sync(0xffffffffu, b, o);
        if (g >= o){
            b = fmaf(a, bp, b);
            a = a * ap;
        }
    }
    float bex = __shfl_up_sync(0xffffffffu, b, 1);
    float h = (g == 0) ? 0.f : bex;

    #pragma unroll
    for (int j=0; j<CPT; j++){
        float q = sH[(ch0+j)*17 + n];
        sH[(ch0+j)*17 + n] = h;
        h = fmaf(Pv[j], h, q);
    }
    __syncthreads();

    float4* dst4 = (float4*)(g_H + (size_t)kd*NC*16);
    for (int i=tid; i<NC*4; i+=512){
        int e = i*4; int ch = e>>4, nn = e&15;
        const float* p = &sH[ch*17+nn];
        dst4[i] = make_float4(p[0], p[1], p[2], p[3]);
    }
}

// ---------------------------------------------------------------------------
// Pass 3: replay chunk with correct h_in, emit y. Writes each k's plane
// pre-reversed / pre-transposed so k_final reads all planes at index l.
// ---------------------------------------------------------------------------
__global__ __launch_bounds__(96) void k_scan3(const float* __restrict__ A_logs,
                                              const float* __restrict__ Ds){
    __shared__ float BC_s[LC*32];
    int k = blockIdx.y, ch = blockIdx.x;
    int c0 = ch*LC;
    int d  = threadIdx.x;
    for (int idx=d; idx<LC*32; idx+=96)
        BC_s[idx] = g_BC[((size_t)k*LL + c0)*32 + idx];
    __syncthreads();

    float Aa[NN];
    #pragma unroll
    for (int n=0;n<NN;n++) Aa[n] = -__expf(A_logs[(k*96+d)*NN + n]);

    int kd = k*96 + d;
    const float4* hp = (const float4*)&g_H[((size_t)kd*NC + ch)*16];
    float4 h0v=hp[0], h1v=hp[1], h2v=hp[2], h3v=hp[3];
    float h[16] = {h0v.x,h0v.y,h0v.z,h0v.w, h1v.x,h1v.y,h1v.z,h1v.w,
                   h2v.x,h2v.y,h2v.z,h2v.w, h3v.x,h3v.y,h3v.z,h3v.w};
    float Dsv = Ds[kd];

    const float2* dxp = g_dx + ((size_t)k*LL + c0)*96 + d;
    float*        pl  = g_y  + (size_t)k*LL*96;
    #pragma unroll 2
    for (int li=0; li<LC; li++){
        float2 dv = dxp[(size_t)li*96];
        float delta = dv.x, xv = dv.y;
        float du = delta*xv;
        const float4* bp = (const float4*)&BC_s[li*32];
        float4 b0=bp[0], b1=bp[1], b2=bp[2], b3=bp[3];
        float4 q0=bp[4], q1=bp[5], q2=bp[6], q3=bp[7];
        float Bv[16] = {b0.x,b0.y,b0.z,b0.w, b1.x,b1.y,b1.z,b1.w,
                        b2.x,b2.y,b2.z,b2.w, b3.x,b3.y,b3.z,b3.w};
        float Cv[16] = {q0.x,q0.y,q0.z,q0.w, q1.x,q1.y,q1.z,q1.w,
                        q2.x,q2.y,q2.z,q2.w, q3.x,q3.y,q3.z,q3.w};
        float y = xv*Dsv;
        #pragma unroll
        for (int n=0;n<NN;n++){
            h[n] = fmaf(h[n], __expf(delta*Aa[n]), du*Bv[n]);
            y    = fmaf(h[n], Cv[n], y);
        }
        int l = c0 + li;
        int slot;
        if      (k == 0) slot = l;
        else if (k == 2) slot = LL-1-l;
        else if (k == 1){ int r = l/96;  slot = (l - r*96)*96 + r; }
        else            { int lm = LL-1-l; int r = lm/96; slot = (lm - r*96)*96 + r; }
        pl[(size_t)slot*96 + d] = y;
    }
}

// ---------------------------------------------------------------------------
// Final: sum 4 pre-aligned planes, layernorm over D=96.
// ---------------------------------------------------------------------------
__global__ __launch_bounds__(384) void k_final(const float* __restrict__ lnw,
                                               const float* __restrict__ lnb,
                                               float* __restrict__ out){
    int t   = threadIdx.x;
    int grp = t / 96;
    int d   = t - grp*96;
    int l   = blockIdx.x*4 + grp;
    size_t base = (size_t)l*96 + d;
    float v = g_y[base]
            + g_y[(size_t)1*LL*96 + base]
            + g_y[(size_t)2*LL*96 + base]
            + g_y[(size_t)3*LL*96 + base];
    float s = v, ss = v*v;
    #pragma unroll
    for (int o=16;o>0;o>>=1){
        s  += __shfl_xor_sync(0xffffffffu, s,  o);
        ss += __shfl_xor_sync(0xffffffffu, ss, o);
    }
    __shared__ float rs[4][3], rss[4][3];
    int wig = d >> 5;
    if ((d&31)==0){ rs[grp][wig]=s; rss[grp][wig]=ss; }
    __syncthreads();
    float tot  = rs[grp][0]+rs[grp][1]+rs[grp][2];
    float tot2 = rss[grp][0]+rss[grp][1]+rss[grp][2];
    float mu  = tot*(1.f/96.f);
    float var = fmaxf(tot2*(1.f/96.f) - mu*mu, 0.f);
    float r   = rsqrtf(var + 1e-5f);
    out[base] = (v-mu)*r*lnw[d] + lnb[d];
}

// ---------------------------------------------------------------------------
extern "C" void kernel_launch(void* const* d_in, const int* in_sizes, int n_in,
                              void* d_out, int out_size)
{
    const float* x   = (const float*)d_in[0];
    const float* W   = (const float*)d_in[1];
    const float* dtw = (const float*)d_in[2];
    const float* dtb = (const float*)d_in[3];
    const float* Al  = (const float*)d_in[4];
    const float* Ds  = (const float*)d_in[5];
    const float* lnw = (const float*)d_in[6];
    const float* lnb = (const float*)d_in[7];
    float* out = (float*)d_out;

    k_transpose<<<dim3(3,3,96), dim3(32,8)>>>(x);
    k_proj     <<<dim3(LL/32, KK), 256>>>(x, W, dtw, dtb, Al);
    k_scan2    <<<KD, 512>>>(Al);
    k_scan3    <<<dim3(NC, KK), 96>>>(Al, Ds);
    k_final    <<<LL/4, 384>>>(lnw, lnb, out);
}

// round 7
// speedup vs baseline: 1.8278x; 1.0498x over previous
#include <cuda_runtime.h>
#include <math.h>

#define DD 96
#define LL 9216
#define KK 4
#define NN 16
#define RR 6
#define CC 38
#define LC 16
#define NC 576   // LL/LC
#define KD 384   // KK*DD
#define LOG2E 1.4426950408889634f

__device__ __forceinline__ float ex2f(float x){
    float y; asm("ex2.approx.f32 %0, %1;" : "=f"(y) : "f"(x)); return y;
}

// scratch (no allocations allowed)
__device__ float  g_xT[DD*LL];          // transposed image per d
__device__ float  g_BC[KK*LL*32];       // (k,l,[B0..15,C0..15])
__device__ float2 g_dx[KK*LL*DD];       // (k,l,d) -> (delta, x)
__device__ float  g_Sd[KD*NC];          // [kd][ch] per-chunk sum of delta
__device__ float  g_H [KD*NC*NN];       // [kd][ch][n] chunk h (pass1) then h_in (pass2)
__device__ float  g_y [KK*LL*DD];       // 4 planes, all aligned to output index l

// ---------------------------------------------------------------------------
// Kernel T: per-d HW transpose of x
// ---------------------------------------------------------------------------
__global__ void k_transpose(const float* __restrict__ x){
    __shared__ float tile[32][33];
    int d  = blockIdx.z;
    int h0 = blockIdx.x*32, w0 = blockIdx.y*32;
    int tx = threadIdx.x,  ty = threadIdx.y;
    const float* xp = x    + (size_t)d*LL;
    float*       op = g_xT + (size_t)d*LL;
    #pragma unroll
    for (int i=0;i<4;i++) tile[ty+8*i][tx] = xp[(h0+ty+8*i)*96 + w0+tx];
    __syncthreads();
    #pragma unroll
    for (int i=0;i<4;i++) op[(w0+ty+8*i)*96 + h0+tx] = tile[tx][ty+8*i];
}

// ---------------------------------------------------------------------------
// Kernel A (fused): projections + chunk-local scan.
// Block = (32 l-values = 2 chunks, one k).
// ---------------------------------------------------------------------------
__global__ __launch_bounds__(256) void k_proj(
    const float* __restrict__ x,  const float* __restrict__ W,
    const float* __restrict__ dtw,const float* __restrict__ dtb,
    const float* __restrict__ A_logs)
{
    __shared__ float xs_s [96*33];
    __shared__ float Wt_s [96*40];   // reused as delta_s (96*33) after GEMM
    __shared__ float dbl_s[40*33];
    __shared__ float Wdt_s[96*6];
    __shared__ float bias_s[96];

    int k   = blockIdx.y;
    int l0  = blockIdx.x*32;
    int tid = threadIdx.x;
    const float* src = (k & 1) ? g_xT : x;

    for (int idx=tid; idx<96*32; idx+=256){
        int d = idx>>5, li = idx&31;
        int l = l0+li;
        int ls = (k<2) ? l : (LL-1-l);
        xs_s[d*33+li] = src[(size_t)d*LL + ls];
    }
    for (int idx=tid; idx<CC*96; idx+=256){
        int c = idx/96, d = idx - c*96;
        Wt_s[d*40+c] = W[(k*CC+c)*96 + d];
    }
    for (int idx=tid; idx<96*6; idx+=256) Wdt_s[idx] = dtw[k*576 + idx];
    if (tid < 96) bias_s[tid] = dtb[k*96 + tid];
    __syncthreads();

    int lane = tid & 31, wrp = tid >> 5;
    #pragma unroll
    for (int qq=0; qq<2; qq++){
        int q = wrp + qq*8;
        if (q < 10){
            int c0 = q*4;
            float ax=0.f, ay=0.f, az=0.f, aw=0.f;
            for (int d=0; d<96; d++){
                float  xv = xs_s[d*33+lane];
                float4 wv = *(const float4*)&Wt_s[d*40+c0];
                ax = fmaf(wv.x, xv, ax); ay = fmaf(wv.y, xv, ay);
                az = fmaf(wv.z, xv, az); aw = fmaf(wv.w, xv, aw);
            }
            dbl_s[(c0+0)*33+lane] = ax;
            dbl_s[(c0+1)*33+lane] = ay;
            dbl_s[(c0+2)*33+lane] = az;
            dbl_s[(c0+3)*33+lane] = aw;
        }
    }
    __syncthreads();   // GEMM done; Wt_s dead -> reuse as delta_s

    float* delta_s = Wt_s;   // [d*33 + li]

    for (int idx=tid; idx<32*32; idx+=256){
        int li = idx>>5, j = idx&31;
        g_BC[((size_t)k*LL + l0+li)*32 + j] = dbl_s[(6+j)*33 + li];
    }
    for (int idx=tid; idx<96*32; idx+=256){
        int d = idx%96, li = idx/96;
        float acc = bias_s[d];
        #pragma unroll
        for (int r=0; r<6; r++) acc = fmaf(dbl_s[r*33+li], Wdt_s[d*6+r], acc);
        float sp = (acc > 20.f) ? acc : log1pf(__expf(acc));
        delta_s[d*33+li] = sp;
        g_dx[((size_t)k*LL + l0+li)*96 + d] = make_float2(sp, xs_s[d*33+li]);
    }
    __syncthreads();

    // fused chunk-local scan: 2 chunks of LC=16, threads 0..191
    if (tid < 192){
        int sub = tid / 96;
        int d   = tid - sub*96;
        int kd  = k*96 + d;
        int ch  = blockIdx.x*2 + sub;
        int lb  = sub*16;

        float Aa2[NN];
        #pragma unroll
        for (int n=0;n<NN;n++) Aa2[n] = -__expf(A_logs[kd*NN + n]) * LOG2E;
        float h[NN];
        #pragma unroll
        for (int n=0;n<NN;n++) h[n] = 0.f;
        float sd = 0.f;

        #pragma unroll 2
        for (int i=0; i<LC; i++){
            int li = lb + i;
            float delta = delta_s[d*33+li];
            float du    = delta * xs_s[d*33+li];
            sd += delta;
            #pragma unroll
            for (int n=0;n<NN;n++)
                h[n] = fmaf(h[n], ex2f(delta*Aa2[n]), du*dbl_s[(6+n)*33+li]);
        }
        g_Sd[(size_t)kd*NC + ch] = sd;
        float4* hp = (float4*)&g_H[((size_t)kd*NC + ch)*16];
        hp[0] = make_float4(h[0] ,h[1] ,h[2] ,h[3] );
        hp[1] = make_float4(h[4] ,h[5] ,h[6] ,h[7] );
        hp[2] = make_float4(h[8] ,h[9] ,h[10],h[11]);
        hp[3] = make_float4(h[12],h[13],h[14],h[15]);
    }
}

// ---------------------------------------------------------------------------
// Pass 2: parallel chunk-combine. One block per (k,d) sequence.
// ---------------------------------------------------------------------------
#define CPT 18
__global__ __launch_bounds__(512) void k_scan2(const float* __restrict__ A_logs){
    __shared__ float sH [NC*17];
    __shared__ float sSd[NC];

    int kd  = blockIdx.x;
    int tid = threadIdx.x;

    const float4* src4 = (const float4*)(g_H + (size_t)kd*NC*16);
    for (int i=tid; i<NC*4; i+=512){
        float4 v = src4[i];
        int e = i*4; int ch = e>>4, n = e&15;
        float* p = &sH[ch*17+n];
        p[0]=v.x; p[1]=v.y; p[2]=v.z; p[3]=v.w;
    }
    const float4* sd4 = (const float4*)(g_Sd + (size_t)kd*NC);
    for (int i=tid; i<NC/4; i+=512){
        float4 v = sd4[i];
        sSd[i*4+0]=v.x; sSd[i*4+1]=v.y; sSd[i*4+2]=v.z; sSd[i*4+3]=v.w;
    }
    __syncthreads();

    int n = tid >> 5;
    int g = tid & 31;
    float Av2 = -__expf(A_logs[kd*16 + n]) * LOG2E;
    int ch0 = g*CPT;

    float Pv[CPT];
    float a = 1.f, b = 0.f;
    #pragma unroll
    for (int j=0; j<CPT; j++){
        float P = ex2f(Av2 * sSd[ch0+j]);
        Pv[j] = P;
        float q = sH[(ch0+j)*17 + n];
        b = fmaf(P, b, q);
        a = a * P;
    }

    #pragma unroll
    for (int o=1; o<32; o<<=1){
        float ap = __shfl_up_sync(0xffffffffu, a, o);
        float bp = __shfl_up_sync(0xffffffffu, b, o);
        if (g >= o){
            b = fmaf(a, bp, b);
            a = a * ap;
        }
    }
    float bex = __shfl_up_sync(0xffffffffu, b, 1);
    float h = (g == 0) ? 0.f : bex;

    #pragma unroll
    for (int j=0; j<CPT; j++){
        float q = sH[(ch0+j)*17 + n];
        sH[(ch0+j)*17 + n] = h;
        h = fmaf(Pv[j], h, q);
    }
    __syncthreads();

    float4* dst4 = (float4*)(g_H + (size_t)kd*NC*16);
    for (int i=tid; i<NC*4; i+=512){
        int e = i*4; int ch = e>>4, nn = e&15;
        const float* p = &sH[ch*17+nn];
        dst4[i] = make_float4(p[0], p[1], p[2], p[3]);
    }
}

// ---------------------------------------------------------------------------
// Pass 3: replay with correct h_in, emit y. 2 chunks per block, 192 threads.
// ex2-based decay, 4-way y accumulators, prefetched (delta,x) stream.
// ---------------------------------------------------------------------------
__global__ __launch_bounds__(192) void k_scan3(const float* __restrict__ A_logs,
                                               const float* __restrict__ Ds){
    __shared__ float BC_s[2*LC*32];
    int k   = blockIdx.y;
    int chb = blockIdx.x;            // 0..287
    int tid = threadIdx.x;
    int sub = tid / 96;
    int d   = tid - sub*96;
    int ch  = chb*2 + sub;
    int c0  = ch*LC;

    // block covers l = chb*32 .. +32 -> contiguous 1024 floats of BC
    for (int idx=tid; idx<2*LC*32; idx+=192)
        BC_s[idx] = g_BC[((size_t)k*LL + chb*32)*32 + idx];
    __syncthreads();

    int kd = k*96 + d;
    float Aa2[NN];
    #pragma unroll
    for (int n=0;n<NN;n++) Aa2[n] = -__expf(A_logs[kd*NN + n]) * LOG2E;

    const float4* hp = (const float4*)&g_H[((size_t)kd*NC + ch)*16];
    float4 h0v=hp[0], h1v=hp[1], h2v=hp[2], h3v=hp[3];
    float h[16] = {h0v.x,h0v.y,h0v.z,h0v.w, h1v.x,h1v.y,h1v.z,h1v.w,
                   h2v.x,h2v.y,h2v.z,h2v.w, h3v.x,h3v.y,h3v.z,h3v.w};
    float Dsv = Ds[kd];

    const float2* dxp = g_dx + ((size_t)k*LL + c0)*96 + d;
    float*        pl  = g_y  + (size_t)k*LL*96;
    const float*  bc  = &BC_s[sub*LC*32];

    float2 dv = dxp[0];
    #pragma unroll 2
    for (int li=0; li<LC; li++){
        float2 nxt = (li < LC-1) ? dxp[(size_t)(li+1)*96] : make_float2(0.f,0.f);
        float delta = dv.x, xv = dv.y;
        float du = delta*xv;
        const float4* bp = (const float4*)&bc[li*32];
        float4 b0=bp[0], b1=bp[1], b2=bp[2], b3=bp[3];
        float4 q0=bp[4], q1=bp[5], q2=bp[6], q3=bp[7];
        float Bv[16] = {b0.x,b0.y,b0.z,b0.w, b1.x,b1.y,b1.z,b1.w,
                        b2.x,b2.y,b2.z,b2.w, b3.x,b3.y,b3.z,b3.w};
        float Cv[16] = {q0.x,q0.y,q0.z,q0.w, q1.x,q1.y,q1.z,q1.w,
                        q2.x,q2.y,q2.z,q2.w, q3.x,q3.y,q3.z,q3.w};
        float y0 = xv*Dsv, y1 = 0.f, y2 = 0.f, y3 = 0.f;
        #pragma unroll
        for (int n=0;n<NN;n+=4){
            h[n+0] = fmaf(h[n+0], ex2f(delta*Aa2[n+0]), du*Bv[n+0]);
            h[n+1] = fmaf(h[n+1], ex2f(delta*Aa2[n+1]), du*Bv[n+1]);
            h[n+2] = fmaf(h[n+2], ex2f(delta*Aa2[n+2]), du*Bv[n+2]);
            h[n+3] = fmaf(h[n+3], ex2f(delta*Aa2[n+3]), du*Bv[n+3]);
            y0 = fmaf(h[n+0], Cv[n+0], y0);
            y1 = fmaf(h[n+1], Cv[n+1], y1);
            y2 = fmaf(h[n+2], Cv[n+2], y2);
            y3 = fmaf(h[n+3], Cv[n+3], y3);
        }
        float y = (y0+y1) + (y2+y3);
        int l = c0 + li;
        int slot;
        if      (k == 0) slot = l;
        else if (k == 2) slot = LL-1-l;
        else if (k == 1){ int r = l/96;  slot = (l - r*96)*96 + r; }
        else            { int lm = LL-1-l; int r = lm/96; slot = (lm - r*96)*96 + r; }
        pl[(size_t)slot*96 + d] = y;
        dv = nxt;
    }
}

// ---------------------------------------------------------------------------
// Final: sum 4 pre-aligned planes, layernorm over D=96.
// ---------------------------------------------------------------------------
__global__ __launch_bounds__(384) void k_final(const float* __restrict__ lnw,
                                               const float* __restrict__ lnb,
                                               float* __restrict__ out){
    int t   = threadIdx.x;
    int grp = t / 96;
    int d   = t - grp*96;
    int l   = blockIdx.x*4 + grp;
    size_t base = (size_t)l*96 + d;
    float v = g_y[base]
            + g_y[(size_t)1*LL*96 + base]
            + g_y[(size_t)2*LL*96 + base]
            + g_y[(size_t)3*LL*96 + base];
    float s = v, ss = v*v;
    #pragma unroll
    for (int o=16;o>0;o>>=1){
        s  += __shfl_xor_sync(0xffffffffu, s,  o);
        ss += __shfl_xor_sync(0xffffffffu, ss, o);
    }
    __shared__ float rs[4][3], rss[4][3];
    int wig = d >> 5;
    if ((d&31)==0){ rs[grp][wig]=s; rss[grp][wig]=ss; }
    __syncthreads();
    float tot  = rs[grp][0]+rs[grp][1]+rs[grp][2];
    float tot2 = rss[grp][0]+rss[grp][1]+rss[grp][2];
    float mu  = tot*(1.f/96.f);
    float var = fmaxf(tot2*(1.f/96.f) - mu*mu, 0.f);
    float r   = rsqrtf(var + 1e-5f);
    out[base] = (v-mu)*r*lnw[d] + lnb[d];
}

// ---------------------------------------------------------------------------
extern "C" void kernel_launch(void* const* d_in, const int* in_sizes, int n_in,
                              void* d_out, int out_size)
{
    const float* x   = (const float*)d_in[0];
    const float* W   = (const float*)d_in[1];
    const float* dtw = (const float*)d_in[2];
    const float* dtb = (const float*)d_in[3];
    const float* Al  = (const float*)d_in[4];
    const float* Ds  = (const float*)d_in[5];
    const float* lnw = (const float*)d_in[6];
    const float* lnb = (const float*)d_in[7];
    float* out = (float*)d_out;

    k_transpose<<<dim3(3,3,96), dim3(32,8)>>>(x);
    k_proj     <<<dim3(LL/32, KK), 256>>>(x, W, dtw, dtb, Al);
    k_scan2    <<<KD, 512>>>(Al);
    k_scan3    <<<dim3(NC/2, KK), 192>>>(Al, Ds);
    k_final    <<<LL/4, 384>>>(lnw, lnb, out);
}

// round 8
// speedup vs baseline: 1.8647x; 1.0202x over previous
#include <cuda_runtime.h>
#include <math.h>

#define DD 96
#define LL 9216
#define KK 4
#define NN 16
#define RR 6
#define CC 38
#define LC 16
#define NC 576   // LL/LC
#define KD 384   // KK*DD
#define LOG2E 1.4426950408889634f

__device__ __forceinline__ float ex2f(float x){
    float y; asm("ex2.approx.f32 %0, %1;" : "=f"(y) : "f"(x)); return y;
}

// scratch (no allocations allowed)
__device__ float  g_xT[DD*LL];          // transposed image per d
__device__ float  g_BC[KK*LL*32];       // (k,l,[B0..15,C0..15])
__device__ float2 g_dx[KK*LL*DD];       // (k,l,d) -> (delta, x)
__device__ float  g_Sd[KD*NC];          // [kd][ch] per-chunk sum of delta
__device__ float  g_H [KD*NC*NN];       // [kd][ch][n] chunk h (pass1) then h_in (pass2)
__device__ float  g_y [KK*LL*DD];       // 4 planes, all aligned to output index l

// ---------------------------------------------------------------------------
// Kernel T: per-d HW transpose of x
// ---------------------------------------------------------------------------
__global__ void k_transpose(const float* __restrict__ x){
    __shared__ float tile[32][33];
    int d  = blockIdx.z;
    int h0 = blockIdx.x*32, w0 = blockIdx.y*32;
    int tx = threadIdx.x,  ty = threadIdx.y;
    const float* xp = x    + (size_t)d*LL;
    float*       op = g_xT + (size_t)d*LL;
    #pragma unroll
    for (int i=0;i<4;i++) tile[ty+8*i][tx] = xp[(h0+ty+8*i)*96 + w0+tx];
    __syncthreads();
    #pragma unroll
    for (int i=0;i<4;i++) op[(w0+ty+8*i)*96 + h0+tx] = tile[tx][ty+8*i];
}

// ---------------------------------------------------------------------------
// Kernel A (fused): projections + chunk-local scan.
// Block = (32 l-values = 2 chunks, one k).
// ---------------------------------------------------------------------------
__global__ __launch_bounds__(256) void k_proj(
    const float* __restrict__ x,  const float* __restrict__ W,
    const float* __restrict__ dtw,const float* __restrict__ dtb,
    const float* __restrict__ A_logs)
{
    __shared__ float xs_s [96*33];
    __shared__ float Wt_s [96*40];   // reused as delta_s (96*33) after GEMM
    __shared__ float dbl_s[40*33];
    __shared__ float Wdt_s[96*6];
    __shared__ float bias_s[96];

    int k   = blockIdx.y;
    int l0  = blockIdx.x*32;
    int tid = threadIdx.x;
    const float* src = (k & 1) ? g_xT : x;

    for (int idx=tid; idx<96*32; idx+=256){
        int d = idx>>5, li = idx&31;
        int l = l0+li;
        int ls = (k<2) ? l : (LL-1-l);
        xs_s[d*33+li] = src[(size_t)d*LL + ls];
    }
    for (int idx=tid; idx<CC*96; idx+=256){
        int c = idx/96, d = idx - c*96;
        Wt_s[d*40+c] = W[(k*CC+c)*96 + d];
    }
    for (int idx=tid; idx<96*6; idx+=256) Wdt_s[idx] = dtw[k*576 + idx];
    if (tid < 96) bias_s[tid] = dtb[k*96 + tid];
    __syncthreads();

    int lane = tid & 31, wrp = tid >> 5;
    #pragma unroll
    for (int qq=0; qq<2; qq++){
        int q = wrp + qq*8;
        if (q < 10){
            int c0 = q*4;
            float ax=0.f, ay=0.f, az=0.f, aw=0.f;
            for (int d=0; d<96; d++){
                float  xv = xs_s[d*33+lane];
                float4 wv = *(const float4*)&Wt_s[d*40+c0];
                ax = fmaf(wv.x, xv, ax); ay = fmaf(wv.y, xv, ay);
                az = fmaf(wv.z, xv, az); aw = fmaf(wv.w, xv, aw);
            }
            dbl_s[(c0+0)*33+lane] = ax;
            dbl_s[(c0+1)*33+lane] = ay;
            dbl_s[(c0+2)*33+lane] = az;
            dbl_s[(c0+3)*33+lane] = aw;
        }
    }
    __syncthreads();   // GEMM done; Wt_s dead -> reuse as delta_s

    float* delta_s = Wt_s;   // [d*33 + li]

    for (int idx=tid; idx<32*32; idx+=256){
        int li = idx>>5, j = idx&31;
        g_BC[((size_t)k*LL + l0+li)*32 + j] = dbl_s[(6+j)*33 + li];
    }
    for (int idx=tid; idx<96*32; idx+=256){
        int d = idx%96, li = idx/96;
        float acc = bias_s[d];
        #pragma unroll
        for (int r=0; r<6; r++) acc = fmaf(dbl_s[r*33+li], Wdt_s[d*6+r], acc);
        float sp = (acc > 20.f) ? acc : log1pf(__expf(acc));
        delta_s[d*33+li] = sp;
        g_dx[((size_t)k*LL + l0+li)*96 + d] = make_float2(sp, xs_s[d*33+li]);
    }
    __syncthreads();

    // fused chunk-local scan: 2 chunks of LC=16, threads 0..191
    if (tid < 192){
        int sub = tid / 96;
        int d   = tid - sub*96;
        int kd  = k*96 + d;
        int ch  = blockIdx.x*2 + sub;
        int lb  = sub*16;

        float Aa2[NN];
        #pragma unroll
        for (int n=0;n<NN;n++) Aa2[n] = -__expf(A_logs[kd*NN + n]) * LOG2E;
        float h[NN];
        #pragma unroll
        for (int n=0;n<NN;n++) h[n] = 0.f;
        float sd = 0.f;

        #pragma unroll 2
        for (int i=0; i<LC; i++){
            int li = lb + i;
            float delta = delta_s[d*33+li];
            float du    = delta * xs_s[d*33+li];
            sd += delta;
            #pragma unroll
            for (int n=0;n<NN;n++)
                h[n] = fmaf(h[n], ex2f(delta*Aa2[n]), du*dbl_s[(6+n)*33+li]);
        }
        g_Sd[(size_t)kd*NC + ch] = sd;
        float4* hp = (float4*)&g_H[((size_t)kd*NC + ch)*16];
        hp[0] = make_float4(h[0] ,h[1] ,h[2] ,h[3] );
        hp[1] = make_float4(h[4] ,h[5] ,h[6] ,h[7] );
        hp[2] = make_float4(h[8] ,h[9] ,h[10],h[11]);
        hp[3] = make_float4(h[12],h[13],h[14],h[15]);
    }
}

// ---------------------------------------------------------------------------
// Pass 2: parallel chunk-combine. One block per (k,d) sequence.
// ---------------------------------------------------------------------------
#define CPT 18
__global__ __launch_bounds__(512) void k_scan2(const float* __restrict__ A_logs){
    __shared__ float sH [NC*17];
    __shared__ float sSd[NC];

    int kd  = blockIdx.x;
    int tid = threadIdx.x;

    const float4* src4 = (const float4*)(g_H + (size_t)kd*NC*16);
    for (int i=tid; i<NC*4; i+=512){
        float4 v = src4[i];
        int e = i*4; int ch = e>>4, n = e&15;
        float* p = &sH[ch*17+n];
        p[0]=v.x; p[1]=v.y; p[2]=v.z; p[3]=v.w;
    }
    const float4* sd4 = (const float4*)(g_Sd + (size_t)kd*NC);
    for (int i=tid; i<NC/4; i+=512){
        float4 v = sd4[i];
        sSd[i*4+0]=v.x; sSd[i*4+1]=v.y; sSd[i*4+2]=v.z; sSd[i*4+3]=v.w;
    }
    __syncthreads();

    int n = tid >> 5;
    int g = tid & 31;
    float Av2 = -__expf(A_logs[kd*16 + n]) * LOG2E;
    int ch0 = g*CPT;

    float Pv[CPT];
    float a = 1.f, b = 0.f;
    #pragma unroll
    for (int j=0; j<CPT; j++){
        float P = ex2f(Av2 * sSd[ch0+j]);
        Pv[j] = P;
        float q = sH[(ch0+j)*17 + n];
        b = fmaf(P, b, q);
        a = a * P;
    }

    #pragma unroll
    for (int o=1; o<32; o<<=1){
        float ap = __shfl_up_sync(0xffffffffu, a, o);
        float bp = __shfl_up_sync(0xffffffffu, b, o);
        if (g >= o){
            b = fmaf(a, bp, b);
            a = a * ap;
        }
    }
    float bex = __shfl_up_sync(0xffffffffu, b, 1);
    float h = (g == 0) ? 0.f : bex;

    #pragma unroll
    for (int j=0; j<CPT; j++){
        float q = sH[(ch0+j)*17 + n];
        sH[(ch0+j)*17 + n] = h;
        h = fmaf(Pv[j], h, q);
    }
    __syncthreads();

    float4* dst4 = (float4*)(g_H + (size_t)kd*NC*16);
    for (int i=tid; i<NC*4; i+=512){
        int e = i*4; int ch = e>>4, nn = e&15;
        const float* p = &sH[ch*17+nn];
        dst4[i] = make_float4(p[0], p[1], p[2], p[3]);
    }
}

// ---------------------------------------------------------------------------
// Pass 3: replay with correct h_in, emit y.
// 384 threads = 2 chunks x 96 d x 2 n-halves. Each thread owns 8 states.
// y combined across the lane pair with one shfl_xor. Scatter slot is
// slot0 + li*stride (each chunk lies inside one image row).
// ---------------------------------------------------------------------------
__global__ __launch_bounds__(384) void k_scan3(const float* __restrict__ A_logs,
                                               const float* __restrict__ Ds){
    __shared__ float BC_s[2*LC*32];
    int k   = blockIdx.y;
    int chb = blockIdx.x;            // 0..287
    int tid = threadIdx.x;
    int sub = tid / 192;
    int r   = tid - sub*192;
    int d   = r >> 1;
    int nh  = r & 1;
    int ch  = chb*2 + sub;
    int c0  = ch*LC;

    for (int idx=tid; idx<2*LC*32; idx+=384)
        BC_s[idx] = g_BC[((size_t)k*LL + chb*32)*32 + idx];
    __syncthreads();

    int kd = k*96 + d;
    int nb = nh*8;
    float Aa2[8];
    #pragma unroll
    for (int j=0;j<8;j++) Aa2[j] = -__expf(A_logs[kd*NN + nb + j]) * LOG2E;

    const float4* hp = (const float4*)&g_H[((size_t)kd*NC + ch)*16 + nb];
    float4 h0v=hp[0], h1v=hp[1];
    float h[8] = {h0v.x,h0v.y,h0v.z,h0v.w, h1v.x,h1v.y,h1v.z,h1v.w};
    float Dsv = Ds[kd];

    // scatter destination: slot0 + li*stride (chunk stays inside one row)
    int slot0, stride;
    if      (k == 0){ slot0 = c0;        stride =  1; }
    else if (k == 2){ slot0 = LL-1-c0;   stride = -1; }
    else if (k == 1){ int rr = c0/96; slot0 = (c0 - rr*96)*96 + rr;  stride =  96; }
    else            { int lm = LL-1-c0; int rr = lm/96;
                      slot0 = (lm - rr*96)*96 + rr;                  stride = -96; }

    const float2* dxp = g_dx + ((size_t)k*LL + c0)*96 + d;
    float*        pp  = g_y  + (size_t)k*LL*96 + (size_t)slot0*96 + d;
    const float*  bc  = &BC_s[sub*LC*32 + nb];
    int pstep = stride*96;

    float2 dv = dxp[0];
    #pragma unroll 2
    for (int li=0; li<LC; li++){
        float2 nxt = (li < LC-1) ? dxp[(size_t)(li+1)*96] : make_float2(0.f,0.f);
        float delta = dv.x, xv = dv.y;
        float du = delta*xv;
        const float4* bp = (const float4*)&bc[li*32];
        float4 b0=bp[0], b1=bp[1];
        float4 q0=bp[4], q1=bp[5];
        float Bv[8] = {b0.x,b0.y,b0.z,b0.w, b1.x,b1.y,b1.z,b1.w};
        float Cv[8] = {q0.x,q0.y,q0.z,q0.w, q1.x,q1.y,q1.z,q1.w};
        float y0=0.f, y1=0.f, y2=0.f, y3=0.f;
        #pragma unroll
        for (int j=0;j<8;j+=4){
            h[j+0] = fmaf(h[j+0], ex2f(delta*Aa2[j+0]), du*Bv[j+0]);
            h[j+1] = fmaf(h[j+1], ex2f(delta*Aa2[j+1]), du*Bv[j+1]);
            h[j+2] = fmaf(h[j+2], ex2f(delta*Aa2[j+2]), du*Bv[j+2]);
            h[j+3] = fmaf(h[j+3], ex2f(delta*Aa2[j+3]), du*Bv[j+3]);
            y0 = fmaf(h[j+0], Cv[j+0], y0);
            y1 = fmaf(h[j+1], Cv[j+1], y1);
            y2 = fmaf(h[j+2], Cv[j+2], y2);
            y3 = fmaf(h[j+3], Cv[j+3], y3);
        }
        float y = (y0+y1)+(y2+y3);
        y += __shfl_xor_sync(0xffffffffu, y, 1);
        if (nh == 0) pp[li*pstep] = y + xv*Dsv;
        dv = nxt;
    }
}

// ---------------------------------------------------------------------------
// Final: sum 4 pre-aligned planes, layernorm over D=96.
// ---------------------------------------------------------------------------
__global__ __launch_bounds__(384) void k_final(const float* __restrict__ lnw,
                                               const float* __restrict__ lnb,
                                               float* __restrict__ out){
    int t   = threadIdx.x;
    int grp = t / 96;
    int d   = t - grp*96;
    int l   = blockIdx.x*4 + grp;
    size_t base = (size_t)l*96 + d;
    float v = g_y[base]
            + g_y[(size_t)1*LL*96 + base]
            + g_y[(size_t)2*LL*96 + base]
            + g_y[(size_t)3*LL*96 + base];
    float s = v, ss = v*v;
    #pragma unroll
    for (int o=16;o>0;o>>=1){
        s  += __shfl_xor_sync(0xffffffffu, s,  o);
        ss += __shfl_xor_sync(0xffffffffu, ss, o);
    }
    __shared__ float rs[4][3], rss[4][3];
    int wig = d >> 5;
    if ((d&31)==0){ rs[grp][wig]=s; rss[grp][wig]=ss; }
    __syncthreads();
    float tot  = rs[grp][0]+rs[grp][1]+rs[grp][2];
    float tot2 = rss[grp][0]+rss[grp][1]+rss[grp][2];
    float mu  = tot*(1.f/96.f);
    float var = fmaxf(tot2*(1.f/96.f) - mu*mu, 0.f);
    float r   = rsqrtf(var + 1e-5f);
    out[base] = (v-mu)*r*lnw[d] + lnb[d];
}

// ---------------------------------------------------------------------------
extern "C" void kernel_launch(void* const* d_in, const int* in_sizes, int n_in,
                              void* d_out, int out_size)
{
    const float* x   = (const float*)d_in[0];
    const float* W   = (const float*)d_in[1];
    const float* dtw = (const float*)d_in[2];
    const float* dtb = (const float*)d_in[3];
    const float* Al  = (const float*)d_in[4];
    const float* Ds  = (const float*)d_in[5];
    const float* lnw = (const float*)d_in[6];
    const float* lnb = (const float*)d_in[7];
    float* out = (float*)d_out;

    k_transpose<<<dim3(3,3,96), dim3(32,8)>>>(x);
    k_proj     <<<dim3(LL/32, KK), 256>>>(x, W, dtw, dtb, Al);
    k_scan2    <<<KD, 512>>>(Al);
    k_scan3    <<<dim3(NC/2, KK), 384>>>(Al, Ds);
    k_final    <<<LL/4, 384>>>(lnw, lnb, out);
}

// round 9
// speedup vs baseline: 1.8707x; 1.0032x over previous
#include <cuda_runtime.h>
#include <math.h>

#define DD 96
#define LL 9216
#define KK 4
#define NN 16
#define RR 6
#define CC 38
#define LC 16
#define NC 576   // LL/LC
#define KD 384   // KK*DD
#define LOG2E 1.4426950408889634f

__device__ __forceinline__ float ex2f(float x){
    float y; asm("ex2.approx.f32 %0, %1;" : "=f"(y) : "f"(x)); return y;
}

// scratch (no allocations allowed)
__device__ float  g_xT[DD*LL];          // transposed image per d
__device__ float  g_BC[KK*LL*32];       // (k,l,[B0..15,C0..15])
__device__ float2 g_dx[KK*LL*DD];       // (k,l,d) -> (delta, x)
__device__ float  g_Sd[KD*NC];          // [kd][ch] per-chunk sum of delta
__device__ float  g_H [KD*NC*NN];       // [kd][ch][n] chunk h (pass1) then h_in (pass2)
__device__ float  g_y [KK*LL*DD];       // 4 planes, all aligned to output index l

// ---------------------------------------------------------------------------
// Kernel T: per-d HW transpose of x
// ---------------------------------------------------------------------------
__global__ void k_transpose(const float* __restrict__ x){
    __shared__ float tile[32][33];
    int d  = blockIdx.z;
    int h0 = blockIdx.x*32, w0 = blockIdx.y*32;
    int tx = threadIdx.x,  ty = threadIdx.y;
    const float* xp = x    + (size_t)d*LL;
    float*       op = g_xT + (size_t)d*LL;
    #pragma unroll
    for (int i=0;i<4;i++) tile[ty+8*i][tx] = xp[(h0+ty+8*i)*96 + w0+tx];
    __syncthreads();
    #pragma unroll
    for (int i=0;i<4;i++) op[(w0+ty+8*i)*96 + h0+tx] = tile[tx][ty+8*i];
}

// ---------------------------------------------------------------------------
// Kernel A (fused): projections + chunk-local scan.
// Block = (32 l-values = 2 chunks, one k).
// ---------------------------------------------------------------------------
__global__ __launch_bounds__(256) void k_proj(
    const float* __restrict__ x,  const float* __restrict__ W,
    const float* __restrict__ dtw,const float* __restrict__ dtb,
    const float* __restrict__ A_logs)
{
    __shared__ float xs_s [96*33];
    __shared__ float Wt_s [96*40];   // reused as delta_s (96*33) after GEMM
    __shared__ float dbl_s[40*33];
    __shared__ float Wdt_s[96*6];
    __shared__ float bias_s[96];

    int k   = blockIdx.y;
    int l0  = blockIdx.x*32;
    int tid = threadIdx.x;
    const float* src = (k & 1) ? g_xT : x;

    for (int idx=tid; idx<96*32; idx+=256){
        int d = idx>>5, li = idx&31;
        int l = l0+li;
        int ls = (k<2) ? l : (LL-1-l);
        xs_s[d*33+li] = src[(size_t)d*LL + ls];
    }
    for (int idx=tid; idx<CC*96; idx+=256){
        int c = idx/96, d = idx - c*96;
        Wt_s[d*40+c] = W[(k*CC+c)*96 + d];
    }
    for (int idx=tid; idx<96*6; idx+=256) Wdt_s[idx] = dtw[k*576 + idx];
    if (tid < 96) bias_s[tid] = dtb[k*96 + tid];
    __syncthreads();

    int lane = tid & 31, wrp = tid >> 5;
    #pragma unroll
    for (int qq=0; qq<2; qq++){
        int q = wrp + qq*8;
        if (q < 10){
            int c0 = q*4;
            float ax=0.f, ay=0.f, az=0.f, aw=0.f;
            for (int d=0; d<96; d++){
                float  xv = xs_s[d*33+lane];
                float4 wv = *(const float4*)&Wt_s[d*40+c0];
                ax = fmaf(wv.x, xv, ax); ay = fmaf(wv.y, xv, ay);
                az = fmaf(wv.z, xv, az); aw = fmaf(wv.w, xv, aw);
            }
            dbl_s[(c0+0)*33+lane] = ax;
            dbl_s[(c0+1)*33+lane] = ay;
            dbl_s[(c0+2)*33+lane] = az;
            dbl_s[(c0+3)*33+lane] = aw;
        }
    }
    __syncthreads();   // GEMM done; Wt_s dead -> reuse as delta_s

    float* delta_s = Wt_s;   // [d*33 + li]

    for (int idx=tid; idx<32*32; idx+=256){
        int li = idx>>5, j = idx&31;
        g_BC[((size_t)k*LL + l0+li)*32 + j] = dbl_s[(6+j)*33 + li];
    }
    for (int idx=tid; idx<96*32; idx+=256){
        int d = idx%96, li = idx/96;
        float acc = bias_s[d];
        #pragma unroll
        for (int r=0; r<6; r++) acc = fmaf(dbl_s[r*33+li], Wdt_s[d*6+r], acc);
        float sp = (acc > 20.f) ? acc : log1pf(__expf(acc));
        delta_s[d*33+li] = sp;
        g_dx[((size_t)k*LL + l0+li)*96 + d] = make_float2(sp, xs_s[d*33+li]);
    }
    __syncthreads();

    // fused chunk-local scan: 2 chunks of LC=16, threads 0..191
    if (tid < 192){
        int sub = tid / 96;
        int d   = tid - sub*96;
        int kd  = k*96 + d;
        int ch  = blockIdx.x*2 + sub;
        int lb  = sub*16;

        float Aa2[NN];
        #pragma unroll
        for (int n=0;n<NN;n++) Aa2[n] = -__expf(A_logs[kd*NN + n]) * LOG2E;
        float h[NN];
        #pragma unroll
        for (int n=0;n<NN;n++) h[n] = 0.f;
        float sd = 0.f;

        #pragma unroll 2
        for (int i=0; i<LC; i++){
            int li = lb + i;
            float delta = delta_s[d*33+li];
            float du    = delta * xs_s[d*33+li];
            sd += delta;
            #pragma unroll
            for (int n=0;n<NN;n++)
                h[n] = fmaf(h[n], ex2f(delta*Aa2[n]), du*dbl_s[(6+n)*33+li]);
        }
        g_Sd[(size_t)kd*NC + ch] = sd;
        float4* hp = (float4*)&g_H[((size_t)kd*NC + ch)*16];
        hp[0] = make_float4(h[0] ,h[1] ,h[2] ,h[3] );
        hp[1] = make_float4(h[4] ,h[5] ,h[6] ,h[7] );
        hp[2] = make_float4(h[8] ,h[9] ,h[10],h[11]);
        hp[3] = make_float4(h[12],h[13],h[14],h[15]);
    }
}

// ---------------------------------------------------------------------------
// Pass 2: parallel chunk-combine. One block per (k,d) sequence.
// ---------------------------------------------------------------------------
#define CPT 18
__global__ __launch_bounds__(512) void k_scan2(const float* __restrict__ A_logs){
    __shared__ float sH [NC*17];
    __shared__ float sSd[NC];

    int kd  = blockIdx.x;
    int tid = threadIdx.x;

    const float4* src4 = (const float4*)(g_H + (size_t)kd*NC*16);
    for (int i=tid; i<NC*4; i+=512){
        float4 v = src4[i];
        int e = i*4; int ch = e>>4, n = e&15;
        float* p = &sH[ch*17+n];
        p[0]=v.x; p[1]=v.y; p[2]=v.z; p[3]=v.w;
    }
    const float4* sd4 = (const float4*)(g_Sd + (size_t)kd*NC);
    for (int i=tid; i<NC/4; i+=512){
        float4 v = sd4[i];
        sSd[i*4+0]=v.x; sSd[i*4+1]=v.y; sSd[i*4+2]=v.z; sSd[i*4+3]=v.w;
    }
    __syncthreads();

    int n = tid >> 5;
    int g = tid & 31;
    float Av2 = -__expf(A_logs[kd*16 + n]) * LOG2E;
    int ch0 = g*CPT;

    float Pv[CPT];
    float a = 1.f, b = 0.f;
    #pragma unroll
    for (int j=0; j<CPT; j++){
        float P = ex2f(Av2 * sSd[ch0+j]);
        Pv[j] = P;
        float q = sH[(ch0+j)*17 + n];
        b = fmaf(P, b, q);
        a = a * P;
    }

    #pragma unroll
    for (int o=1; o<32; o<<=1){
        float ap = __shfl_up_sync(0xffffffffu, a, o);
        float bp = __shfl_up_sync(0xffffffffu, b, o);
        if (g >= o){
            b = fmaf(a, bp, b);
            a = a * ap;
        }
    }
    float bex = __shfl_up_sync(0xffffffffu, b, 1);
    float h = (g == 0) ? 0.f : bex;

    #pragma unroll
    for (int j=0; j<CPT; j++){
        float q = sH[(ch0+j)*17 + n];
        sH[(ch0+j)*17 + n] = h;
        h = fmaf(Pv[j], h, q);
    }
    __syncthreads();

    float4* dst4 = (float4*)(g_H + (size_t)kd*NC*16);
    for (int i=tid; i<NC*4; i+=512){
        int e = i*4; int ch = e>>4, nn = e&15;
        const float* p = &sH[ch*17+nn];
        dst4[i] = make_float4(p[0], p[1], p[2], p[3]);
    }
}

// ---------------------------------------------------------------------------
// Pass 3: replay with correct h_in, emit y.
// Templated on direction k -> compile-time scatter stride; fully unrolled
// inner loop -> all smem/gmem offsets become immediates (no per-step ALU).
// 384 threads = 2 chunks x 96 d x 2 n-halves; 8 states per thread.
// ---------------------------------------------------------------------------
template<int KI>
__device__ __forceinline__ void scan3_body(const float* __restrict__ A_logs,
                                           const float* __restrict__ Ds,
                                           const float* __restrict__ BC_s,
                                           int chb){
    int tid = threadIdx.x;
    int sub = tid / 192;
    int r   = tid - sub*192;
    int d   = r >> 1;
    int nh  = r & 1;
    int ch  = chb*2 + sub;
    int c0  = ch*LC;

    int kd = KI*96 + d;
    int nb = nh*8;
    float Aa2[8];
    #pragma unroll
    for (int j=0;j<8;j++) Aa2[j] = -__expf(A_logs[kd*NN + nb + j]) * LOG2E;

    const float4* hp = (const float4*)&g_H[((size_t)kd*NC + ch)*16 + nb];
    float4 h0v=hp[0], h1v=hp[1];
    float h[8] = {h0v.x,h0v.y,h0v.z,h0v.w, h1v.x,h1v.y,h1v.z,h1v.w};
    float Dsv = Ds[kd];

    // compile-time plane stride per direction
    constexpr int PSTEP = (KI==0) ? 96 : (KI==2) ? -96 : (KI==1) ? 9216 : -9216;
    int slot0;
    if      (KI == 0) slot0 = c0;
    else if (KI == 2) slot0 = LL-1-c0;
    else if (KI == 1){ int rr = c0/96; slot0 = (c0 - rr*96)*96 + rr; }
    else             { int lm = LL-1-c0; int rr = lm/96; slot0 = (lm - rr*96)*96 + rr; }

    const float2* dxp = g_dx + ((size_t)KI*LL + c0)*96 + d;
    float*        pp  = g_y  + (size_t)KI*LL*96 + (size_t)slot0*96 + d;
    const float*  bc  = &BC_s[sub*LC*32 + nb];

    #pragma unroll
    for (int li=0; li<LC; li++){
        float2 dv = dxp[li*96];
        float delta = dv.x, xv = dv.y;
        float du = delta*xv;
        const float4* bp = (const float4*)&bc[li*32];
        float4 b0=bp[0], b1=bp[1];
        float4 q0=bp[4], q1=bp[5];
        float Bv[8] = {b0.x,b0.y,b0.z,b0.w, b1.x,b1.y,b1.z,b1.w};
        float Cv[8] = {q0.x,q0.y,q0.z,q0.w, q1.x,q1.y,q1.z,q1.w};
        float y0=0.f, y1=0.f, y2=0.f, y3=0.f;
        #pragma unroll
        for (int j=0;j<8;j+=4){
            h[j+0] = fmaf(h[j+0], ex2f(delta*Aa2[j+0]), du*Bv[j+0]);
            h[j+1] = fmaf(h[j+1], ex2f(delta*Aa2[j+1]), du*Bv[j+1]);
            h[j+2] = fmaf(h[j+2], ex2f(delta*Aa2[j+2]), du*Bv[j+2]);
            h[j+3] = fmaf(h[j+3], ex2f(delta*Aa2[j+3]), du*Bv[j+3]);
            y0 = fmaf(h[j+0], Cv[j+0], y0);
            y1 = fmaf(h[j+1], Cv[j+1], y1);
            y2 = fmaf(h[j+2], Cv[j+2], y2);
            y3 = fmaf(h[j+3], Cv[j+3], y3);
        }
        float y = (y0+y1)+(y2+y3);
        y += __shfl_xor_sync(0xffffffffu, y, 1);
        if (nh == 0) pp[li*PSTEP] = y + xv*Dsv;
    }
}

__global__ __launch_bounds__(384) void k_scan3(const float* __restrict__ A_logs,
                                               const float* __restrict__ Ds){
    __shared__ float BC_s[2*LC*32];
    int k   = blockIdx.y;
    int chb = blockIdx.x;
    int tid = threadIdx.x;

    for (int idx=tid; idx<2*LC*32; idx+=384)
        BC_s[idx] = g_BC[((size_t)k*LL + chb*32)*32 + idx];
    __syncthreads();

    switch(k){
        case 0: scan3_body<0>(A_logs, Ds, BC_s, chb); break;
        case 1: scan3_body<1>(A_logs, Ds, BC_s, chb); break;
        case 2: scan3_body<2>(A_logs, Ds, BC_s, chb); break;
        default: scan3_body<3>(A_logs, Ds, BC_s, chb); break;
    }
}

// ---------------------------------------------------------------------------
// Final: sum 4 pre-aligned planes, layernorm over D=96.
// ---------------------------------------------------------------------------
__global__ __launch_bounds__(384) void k_final(const float* __restrict__ lnw,
                                               const float* __restrict__ lnb,
                                               float* __restrict__ out){
    int t   = threadIdx.x;
    int grp = t / 96;
    int d   = t - grp*96;
    int l   = blockIdx.x*4 + grp;
    size_t base = (size_t)l*96 + d;
    float v = g_y[base]
            + g_y[(size_t)1*LL*96 + base]
            + g_y[(size_t)2*LL*96 + base]
            + g_y[(size_t)3*LL*96 + base];
    float s = v, ss = v*v;
    #pragma unroll
    for (int o=16;o>0;o>>=1){
        s  += __shfl_xor_sync(0xffffffffu, s,  o);
        ss += __shfl_xor_sync(0xffffffffu, ss, o);
    }
    __shared__ float rs[4][3], rss[4][3];
    int wig = d >> 5;
    if ((d&31)==0){ rs[grp][wig]=s; rss[grp][wig]=ss; }
    __syncthreads();
    float tot  = rs[grp][0]+rs[grp][1]+rs[grp][2];
    float tot2 = rss[grp][0]+rss[grp][1]+rss[grp][2];
    float mu  = tot*(1.f/96.f);
    float var = fmaxf(tot2*(1.f/96.f) - mu*mu, 0.f);
    float r   = rsqrtf(var + 1e-5f);
    out[base] = (v-mu)*r*lnw[d] + lnb[d];
}

// ---------------------------------------------------------------------------
extern "C" void kernel_launch(void* const* d_in, const int* in_sizes, int n_in,
                              void* d_out, int out_size)
{
    const float* x   = (const float*)d_in[0];
    const float* W   = (const float*)d_in[1];
    const float* dtw = (const float*)d_in[2];
    const float* dtb = (const float*)d_in[3];
    const float* Al  = (const float*)d_in[4];
    const float* Ds  = (const float*)d_in[5];
    const float* lnw = (const float*)d_in[6];
    const float* lnb = (const float*)d_in[7];
    float* out = (float*)d_out;

    k_transpose<<<dim3(3,3,96), dim3(32,8)>>>(x);
    k_proj     <<<dim3(LL/32, KK), 256>>>(x, W, dtw, dtb, Al);
    k_scan2    <<<KD, 512>>>(Al);
    k_scan3    <<<dim3(NC/2, KK), 384>>>(Al, Ds);
    k_final    <<<LL/4, 384>>>(lnw, lnb, out);
}

// round 10
// speedup vs baseline: 2.1052x; 1.1254x over previous
#include <cuda_runtime.h>
#include <math.h>

#define DD 96
#define LL 9216
#define KK 4
#define NN 16
#define RR 6
#define CC 38
#define LC 16
#define NC 576   // LL/LC
#define KD 384   // KK*DD
#define LOG2E 1.4426950408889634f

__device__ __forceinline__ float ex2f(float x){
    float y; asm("ex2.approx.f32 %0, %1;" : "=f"(y) : "f"(x)); return y;
}

// scratch (no allocations allowed)
__device__ float  g_xT[DD*LL];          // transposed image per d
__device__ float  g_BC[KK*LL*32];       // (k,l,[B0..15,C0..15])
__device__ float2 g_dx[KK*LL*DD];       // (k,l,d) -> (delta, x)
__device__ float  g_Sd[KD*NC];          // [kd][ch] per-chunk sum of delta
__device__ float  g_H [KD*NC*NN];       // [kd][ch][n] chunk h (pass1) then h_in (pass2)
__device__ float  g_y [KK*LL*DD];       // 4 planes, all aligned to output index l

// ---------------------------------------------------------------------------
// Kernel T: per-d HW transpose of x
// ---------------------------------------------------------------------------
__global__ void k_transpose(const float* __restrict__ x){
    __shared__ float tile[32][33];
    int d  = blockIdx.z;
    int h0 = blockIdx.x*32, w0 = blockIdx.y*32;
    int tx = threadIdx.x,  ty = threadIdx.y;
    const float* xp = x    + (size_t)d*LL;
    float*       op = g_xT + (size_t)d*LL;
    #pragma unroll
    for (int i=0;i<4;i++) tile[ty+8*i][tx] = xp[(h0+ty+8*i)*96 + w0+tx];
    __syncthreads();
    #pragma unroll
    for (int i=0;i<4;i++) op[(w0+ty+8*i)*96 + h0+tx] = tile[tx][ty+8*i];
}

// ---------------------------------------------------------------------------
// Kernel A (fused): projections + chunk-local scan.
// 384 threads: GEMM uses 10 of 12 warps (one column-group each, single pass);
// fused scan uses all 384 (2 chunks x 96 d x 2 n-halves, 8 states/thread).
// ---------------------------------------------------------------------------
__global__ __launch_bounds__(384) void k_proj(
    const float* __restrict__ x,  const float* __restrict__ W,
    const float* __restrict__ dtw,const float* __restrict__ dtb,
    const float* __restrict__ A_logs)
{
    __shared__ float xs_s [96*33];
    __shared__ float Wt_s [96*40];   // reused as delta_s (96*33) after GEMM
    __shared__ float dbl_s[40*33];
    __shared__ float Wdt_s[96*6];
    __shared__ float bias_s[96];

    int k   = blockIdx.y;
    int l0  = blockIdx.x*32;
    int tid = threadIdx.x;
    const float* src = (k & 1) ? g_xT : x;

    for (int idx=tid; idx<96*32; idx+=384){
        int d = idx>>5, li = idx&31;
        int l = l0+li;
        int ls = (k<2) ? l : (LL-1-l);
        xs_s[d*33+li] = src[(size_t)d*LL + ls];
    }
    for (int idx=tid; idx<CC*96; idx+=384){
        int c = idx/96, d = idx - c*96;
        Wt_s[d*40+c] = W[(k*CC+c)*96 + d];
    }
    for (int idx=tid; idx<96*6; idx+=384) Wdt_s[idx] = dtw[k*576 + idx];
    if (tid < 96) bias_s[tid] = dtb[k*96 + tid];
    __syncthreads();

    int lane = tid & 31, wrp = tid >> 5;
    if (wrp < 10){
        int c0 = wrp*4;
        float ax=0.f, ay=0.f, az=0.f, aw=0.f;
        for (int d=0; d<96; d++){
            float  xv = xs_s[d*33+lane];
            float4 wv = *(const float4*)&Wt_s[d*40+c0];
            ax = fmaf(wv.x, xv, ax); ay = fmaf(wv.y, xv, ay);
            az = fmaf(wv.z, xv, az); aw = fmaf(wv.w, xv, aw);
        }
        dbl_s[(c0+0)*33+lane] = ax;
        dbl_s[(c0+1)*33+lane] = ay;
        dbl_s[(c0+2)*33+lane] = az;
        dbl_s[(c0+3)*33+lane] = aw;
    }
    __syncthreads();   // GEMM done; Wt_s dead -> reuse as delta_s

    float* delta_s = Wt_s;   // [d*33 + li]

    for (int idx=tid; idx<32*32; idx+=384){
        int li = idx>>5, j = idx&31;
        g_BC[((size_t)k*LL + l0+li)*32 + j] = dbl_s[(6+j)*33 + li];
    }
    for (int idx=tid; idx<96*32; idx+=384){
        int d = idx%96, li = idx/96;
        float acc = bias_s[d];
        #pragma unroll
        for (int r=0; r<6; r++) acc = fmaf(dbl_s[r*33+li], Wdt_s[d*6+r], acc);
        float sp = (acc > 20.f) ? acc : log1pf(__expf(acc));
        delta_s[d*33+li] = sp;
        g_dx[((size_t)k*LL + l0+li)*96 + d] = make_float2(sp, xs_s[d*33+li]);
    }
    __syncthreads();

    // fused chunk-local scan, n-split: thread = (chunk-sub, d, n-half)
    {
        int sub = tid / 192;
        int r   = tid - sub*192;
        int d   = r >> 1;
        int nh  = r & 1;
        int kd  = k*96 + d;
        int ch  = blockIdx.x*2 + sub;
        int lb  = sub*16;
        int nb  = nh*8;

        float Aa2[8];
        #pragma unroll
        for (int j=0;j<8;j++) Aa2[j] = -__expf(A_logs[kd*NN + nb + j]) * LOG2E;
        float h[8];
        #pragma unroll
        for (int j=0;j<8;j++) h[j] = 0.f;
        float sd = 0.f;

        #pragma unroll
        for (int i=0; i<LC; i++){
            int li = lb + i;
            float delta = delta_s[d*33+li];
            float du    = delta * xs_s[d*33+li];
            sd += delta;
            #pragma unroll
            for (int j=0;j<8;j++)
                h[j] = fmaf(h[j], ex2f(delta*Aa2[j]), du*dbl_s[(6+nb+j)*33+li]);
        }
        if (nh == 0) g_Sd[(size_t)kd*NC + ch] = sd;
        float4* hp = (float4*)&g_H[((size_t)kd*NC + ch)*16 + nb];
        hp[0] = make_float4(h[0], h[1], h[2], h[3]);
        hp[1] = make_float4(h[4], h[5], h[6], h[7]);
    }
}

// ---------------------------------------------------------------------------
// Pass 2: parallel chunk-combine. One block per (k,d) sequence.
// ---------------------------------------------------------------------------
#define CPT 18
__global__ __launch_bounds__(512) void k_scan2(const float* __restrict__ A_logs){
    __shared__ float sH [NC*17];
    __shared__ float sSd[NC];

    int kd  = blockIdx.x;
    int tid = threadIdx.x;

    const float4* src4 = (const float4*)(g_H + (size_t)kd*NC*16);
    for (int i=tid; i<NC*4; i+=512){
        float4 v = src4[i];
        int e = i*4; int ch = e>>4, n = e&15;
        float* p = &sH[ch*17+n];
        p[0]=v.x; p[1]=v.y; p[2]=v.z; p[3]=v.w;
    }
    const float4* sd4 = (const float4*)(g_Sd + (size_t)kd*NC);
    for (int i=tid; i<NC/4; i+=512){
        float4 v = sd4[i];
        sSd[i*4+0]=v.x; sSd[i*4+1]=v.y; sSd[i*4+2]=v.z; sSd[i*4+3]=v.w;
    }
    __syncthreads();

    int n = tid >> 5;
    int g = tid & 31;
    float Av2 = -__expf(A_logs[kd*16 + n]) * LOG2E;
    int ch0 = g*CPT;

    float Pv[CPT];
    float a = 1.f, b = 0.f;
    #pragma unroll
    for (int j=0; j<CPT; j++){
        float P = ex2f(Av2 * sSd[ch0+j]);
        Pv[j] = P;
        float q = sH[(ch0+j)*17 + n];
        b = fmaf(P, b, q);
        a = a * P;
    }

    #pragma unroll
    for (int o=1; o<32; o<<=1){
        float ap = __shfl_up_sync(0xffffffffu, a, o);
        float bp = __shfl_up_sync(0xffffffffu, b, o);
        if (g >= o){
            b = fmaf(a, bp, b);
            a = a * ap;
        }
    }
    float bex = __shfl_up_sync(0xffffffffu, b, 1);
    float h = (g == 0) ? 0.f : bex;

    #pragma unroll
    for (int j=0; j<CPT; j++){
        float q = sH[(ch0+j)*17 + n];
        sH[(ch0+j)*17 + n] = h;
        h = fmaf(Pv[j], h, q);
    }
    __syncthreads();

    float4* dst4 = (float4*)(g_H + (size_t)kd*NC*16);
    for (int i=tid; i<NC*4; i+=512){
        int e = i*4; int ch = e>>4, nn = e&15;
        const float* p = &sH[ch*17+nn];
        dst4[i] = make_float4(p[0], p[1], p[2], p[3]);
    }
}

// ---------------------------------------------------------------------------
// Pass 3: replay with correct h_in, emit y (templated direction, unrolled).
// ---------------------------------------------------------------------------
template<int KI>
__device__ __forceinline__ void scan3_body(const float* __restrict__ A_logs,
                                           const float* __restrict__ Ds,
                                           const float* __restrict__ BC_s,
                                           int chb){
    int tid = threadIdx.x;
    int sub = tid / 192;
    int r   = tid - sub*192;
    int d   = r >> 1;
    int nh  = r & 1;
    int ch  = chb*2 + sub;
    int c0  = ch*LC;

    int kd = KI*96 + d;
    int nb = nh*8;
    float Aa2[8];
    #pragma unroll
    for (int j=0;j<8;j++) Aa2[j] = -__expf(A_logs[kd*NN + nb + j]) * LOG2E;

    const float4* hp = (const float4*)&g_H[((size_t)kd*NC + ch)*16 + nb];
    float4 h0v=hp[0], h1v=hp[1];
    float h[8] = {h0v.x,h0v.y,h0v.z,h0v.w, h1v.x,h1v.y,h1v.z,h1v.w};
    float Dsv = Ds[kd];

    constexpr int PSTEP = (KI==0) ? 96 : (KI==2) ? -96 : (KI==1) ? 9216 : -9216;
    int slot0;
    if      (KI == 0) slot0 = c0;
    else if (KI == 2) slot0 = LL-1-c0;
    else if (KI == 1){ int rr = c0/96; slot0 = (c0 - rr*96)*96 + rr; }
    else             { int lm = LL-1-c0; int rr = lm/96; slot0 = (lm - rr*96)*96 + rr; }

    const float2* dxp = g_dx + ((size_t)KI*LL + c0)*96 + d;
    float*        pp  = g_y  + (size_t)KI*LL*96 + (size_t)slot0*96 + d;
    const float*  bc  = &BC_s[sub*LC*32 + nb];

    #pragma unroll
    for (int li=0; li<LC; li++){
        float2 dv = dxp[li*96];
        float delta = dv.x, xv = dv.y;
        float du = delta*xv;
        const float4* bp = (const float4*)&bc[li*32];
        float4 b0=bp[0], b1=bp[1];
        float4 q0=bp[4], q1=bp[5];
        float Bv[8] = {b0.x,b0.y,b0.z,b0.w, b1.x,b1.y,b1.z,b1.w};
        float Cv[8] = {q0.x,q0.y,q0.z,q0.w, q1.x,q1.y,q1.z,q1.w};
        float y0=0.f, y1=0.f, y2=0.f, y3=0.f;
        #pragma unroll
        for (int j=0;j<8;j+=4){
            h[j+0] = fmaf(h[j+0], ex2f(delta*Aa2[j+0]), du*Bv[j+0]);
            h[j+1] = fmaf(h[j+1], ex2f(delta*Aa2[j+1]), du*Bv[j+1]);
            h[j+2] = fmaf(h[j+2], ex2f(delta*Aa2[j+2]), du*Bv[j+2]);
            h[j+3] = fmaf(h[j+3], ex2f(delta*Aa2[j+3]), du*Bv[j+3]);
            y0 = fmaf(h[j+0], Cv[j+0], y0);
            y1 = fmaf(h[j+1], Cv[j+1], y1);
            y2 = fmaf(h[j+2], Cv[j+2], y2);
            y3 = fmaf(h[j+3], Cv[j+3], y3);
        }
        float y = (y0+y1)+(y2+y3);
        y += __shfl_xor_sync(0xffffffffu, y, 1);
        if (nh == 0) pp[li*PSTEP] = y + xv*Dsv;
    }
}

__global__ __launch_bounds__(384) void k_scan3(const float* __restrict__ A_logs,
                                               const float* __restrict__ Ds){
    __shared__ float BC_s[2*LC*32];
    int k   = blockIdx.y;
    int chb = blockIdx.x;
    int tid = threadIdx.x;

    for (int idx=tid; idx<2*LC*32; idx+=384)
        BC_s[idx] = g_BC[((size_t)k*LL + chb*32)*32 + idx];
    __syncthreads();

    switch(k){
        case 0: scan3_body<0>(A_logs, Ds, BC_s, chb); break;
        case 1: scan3_body<1>(A_logs, Ds, BC_s, chb); break;
        case 2: scan3_body<2>(A_logs, Ds, BC_s, chb); break;
        default: scan3_body<3>(A_logs, Ds, BC_s, chb); break;
    }
}

// ---------------------------------------------------------------------------
// Final: warp per output row l. Lanes 0..23 each own 4 d-values (float4).
// Sum 4 planes with LDG.128, full-warp LN reduction, float4 store.
// ---------------------------------------------------------------------------
__global__ __launch_bounds__(256) void k_final(const float* __restrict__ lnw,
                                               const float* __restrict__ lnb,
                                               float* __restrict__ out){
    int lane = threadIdx.x & 31;
    int wrp  = threadIdx.x >> 5;
    int l    = blockIdx.x*8 + wrp;

    float4 v = make_float4(0.f,0.f,0.f,0.f);
    size_t base = (size_t)l*96 + lane*4;
    if (lane < 24){
        const float4* p0 = (const float4*)(g_y + base);
        const float4* p1 = (const float4*)(g_y + (size_t)1*LL*96 + base);
        const float4* p2 = (const float4*)(g_y + (size_t)2*LL*96 + base);
        const float4* p3 = (const float4*)(g_y + (size_t)3*LL*96 + base);
        float4 a = p0[0], b = p1[0], c = p2[0], e = p3[0];
        v.x = (a.x+b.x)+(c.x+e.x);
        v.y = (a.y+b.y)+(c.y+e.y);
        v.z = (a.z+b.z)+(c.z+e.z);
        v.w = (a.w+b.w)+(c.w+e.w);
    }
    float s  = (v.x+v.y)+(v.z+v.w);
    float ss = (v.x*v.x+v.y*v.y)+(v.z*v.z+v.w*v.w);
    #pragma unroll
    for (int o=16;o>0;o>>=1){
        s  += __shfl_xor_sync(0xffffffffu, s,  o);
        ss += __shfl_xor_sync(0xffffffffu, ss, o);
    }
    float mu  = s*(1.f/96.f);
    float var = fmaxf(ss*(1.f/96.f) - mu*mu, 0.f);
    float rr  = rsqrtf(var + 1e-5f);
    if (lane < 24){
        float4 w = *(const float4*)(lnw + lane*4);
        float4 b = *(const float4*)(lnb + lane*4);
        float4 o4;
        o4.x = (v.x-mu)*rr*w.x + b.x;
        o4.y = (v.y-mu)*rr*w.y + b.y;
        o4.z = (v.z-mu)*rr*w.z + b.z;
        o4.w = (v.w-mu)*rr*w.w + b.w;
        *(float4*)(out + base) = o4;
    }
}

// ---------------------------------------------------------------------------
extern "C" void kernel_launch(void* const* d_in, const int* in_sizes, int n_in,
                              void* d_out, int out_size)
{
    const float* x   = (const float*)d_in[0];
    const float* W   = (const float*)d_in[1];
    const float* dtw = (const float*)d_in[2];
    const float* dtb = (const float*)d_in[3];
    const float* Al  = (const float*)d_in[4];
    const float* Ds  = (const float*)d_in[5];
    const float* lnw = (const float*)d_in[6];
    const float* lnb = (const float*)d_in[7];
    float* out = (float*)d_out;

    k_transpose<<<dim3(3,3,96), dim3(32,8)>>>(x);
    k_proj     <<<dim3(LL/32, KK), 384>>>(x, W, dtw, dtb, Al);
    k_scan2    <<<KD, 512>>>(Al);
    k_scan3    <<<dim3(NC/2, KK), 384>>>(Al, Ds);
    k_final    <<<LL/8, 256>>>(lnw, lnb, out);
}